// round 1
// baseline (speedup 1.0000x reference)
#include <cuda_runtime.h>
#include <cuda_bf16.h>
#include <math.h>

#define NPIX 16384          // 128*128
#define HW   128

// ---------------- static device scratch (no allocations allowed) ----------------
__device__ float  g_cc [512 * NPIX];           // [xu(256) ; Cf(256)]
__device__ float  g_ccp[512 * 130 * 130];      // zero-padded cc
__device__ float  g_v  [256 * NPIX];
__device__ float  g_u  [256 * NPIX];
__device__ float  g_off[ 18 * NPIX];
__device__ int4   g_idx[9 * NPIX];
__device__ float4 g_wt [9 * NPIX];
__device__ float  g_B  [4608 * NPIX];          // 302 MB shared scratch: im2col / gathered samples
__device__ float  g_fam[256 * NPIX];
__device__ float  g_bnscale[512];
__device__ float  g_bnbias [512];

// ---------------- BN coefficient precompute ----------------
__global__ void bncoef_k(const float* __restrict__ g1, const float* __restrict__ b1,
                         const float* __restrict__ m1, const float* __restrict__ v1,
                         const float* __restrict__ g2, const float* __restrict__ b2,
                         const float* __restrict__ m2, const float* __restrict__ v2)
{
    int i = threadIdx.x;
    if (i < 256) {
        float s = g1[i] / sqrtf(v1[i] + 1e-5f);
        g_bnscale[i] = s;
        g_bnbias[i]  = b1[i] - m1[i] * s;
    } else {
        int j = i - 256;
        float s = g2[j] / sqrtf(v2[j] + 1e-5f);
        g_bnscale[i] = s;
        g_bnbias[i]  = b2[j] - m2[j] * s;
    }
}

// ---------------- bilinear upsample 32x32 -> 128x128, align_corners=True ----------------
__global__ void upsample_k(const float* __restrict__ x)
{
    int t = blockIdx.x * 256 + threadIdx.x;      // 256*16384 threads
    int pix = t & (NPIX - 1);
    int c   = t >> 14;
    int oy = pix >> 7, ox = pix & 127;
    const float s = 31.0f / 127.0f;
    float fy = oy * s, fx = ox * s;
    int y0 = (int)floorf(fy); int y1 = min(y0 + 1, 31);
    int x0 = (int)floorf(fx); int x1 = min(x0 + 1, 31);
    float wy = fy - (float)y0;
    float wx = fx - (float)x0;
    const float* xc = x + c * 1024;
    float v00 = xc[y0 * 32 + x0], v01 = xc[y0 * 32 + x1];
    float v10 = xc[y1 * 32 + x0], v11 = xc[y1 * 32 + x1];
    float r0 = v00 * (1.0f - wy) + v10 * wy;
    float r1 = v01 * (1.0f - wy) + v11 * wy;
    g_cc[t] = r0 * (1.0f - wx) + r1 * wx;
}

// ---------------- generic tiled SGEMM: C(MxNPIX) = epi(A(MxK) @ B(KxNPIX)) ----------------
// EPI: 0 none, 1 sigmoid, 2 +residual(e1 full map), 3 relu(x*e1[row]+e2[row])
template<int EPI>
__global__ void __launch_bounds__(256, 2) sgemm_epi(
    const float* __restrict__ A, const float* __restrict__ B, float* __restrict__ C,
    int K, const float* __restrict__ e1, const float* __restrict__ e2)
{
    __shared__ float As[16][128];
    __shared__ float Bs[16][128];
    const int tid  = threadIdx.x;
    const int brow = blockIdx.y * 128;
    const int bcol = blockIdx.x * 128;
    const int ty = tid >> 4, tx = tid & 15;

    float acc[8][8];
#pragma unroll
    for (int i = 0; i < 8; i++)
#pragma unroll
        for (int j = 0; j < 8; j++) acc[i][j] = 0.0f;

    for (int k0 = 0; k0 < K; k0 += 16) {
#pragma unroll
        for (int l = 0; l < 2; l++) {
            int f = tid + l * 256;
            int ar = f >> 2, akq = f & 3;
            float4 av = *(const float4*)(A + (size_t)(brow + ar) * K + k0 + akq * 4);
            As[akq * 4 + 0][ar] = av.x;
            As[akq * 4 + 1][ar] = av.y;
            As[akq * 4 + 2][ar] = av.z;
            As[akq * 4 + 3][ar] = av.w;
            int bkr = f >> 5, bcq = f & 31;
            *(float4*)(&Bs[bkr][bcq * 4]) =
                *(const float4*)(B + (size_t)(k0 + bkr) * NPIX + bcol + bcq * 4);
        }
        __syncthreads();
#pragma unroll
        for (int kk = 0; kk < 16; kk++) {
            float ra[8], rb[8];
#pragma unroll
            for (int i = 0; i < 8; i++) ra[i] = As[kk][ty * 8 + i];
#pragma unroll
            for (int j = 0; j < 8; j++) rb[j] = Bs[kk][tx * 8 + j];
#pragma unroll
            for (int i = 0; i < 8; i++)
#pragma unroll
                for (int j = 0; j < 8; j++)
                    acc[i][j] = fmaf(ra[i], rb[j], acc[i][j]);
        }
        __syncthreads();
    }

#pragma unroll
    for (int i = 0; i < 8; i++) {
        int row = brow + ty * 8 + i;
#pragma unroll
        for (int j = 0; j < 8; j++) {
            int col = bcol + tx * 8 + j;
            float v = acc[i][j];
            if (EPI == 1) v = 1.0f / (1.0f + expf(-v));
            if (EPI == 2) v += e1[(size_t)row * NPIX + col];
            if (EPI == 3) { v = v * e1[row] + e2[row]; v = v > 0.0f ? v : 0.0f; }
            C[(size_t)row * NPIX + col] = v;
        }
    }
}

// ---------------- per-channel 128x128x128 matmul: u[c] = llf[c] @ v[c] + llf[c] ----------------
__global__ void __launch_bounds__(256, 2) chan_matmul(const float* __restrict__ llf)
{
    const int c = blockIdx.x;
    const float* A = llf + (size_t)c * NPIX;   // [h][k]
    const float* B = g_v + (size_t)c * NPIX;   // [k][w]
    float*       C = g_u + (size_t)c * NPIX;

    __shared__ float As[16][128];
    __shared__ float Bs[16][128];
    const int tid = threadIdx.x;
    const int ty = tid >> 4, tx = tid & 15;

    float acc[8][8];
#pragma unroll
    for (int i = 0; i < 8; i++)
#pragma unroll
        for (int j = 0; j < 8; j++) acc[i][j] = 0.0f;

    for (int k0 = 0; k0 < 128; k0 += 16) {
#pragma unroll
        for (int l = 0; l < 2; l++) {
            int f = tid + l * 256;
            int ar = f >> 2, akq = f & 3;
            float4 av = *(const float4*)(A + ar * 128 + k0 + akq * 4);
            As[akq * 4 + 0][ar] = av.x;
            As[akq * 4 + 1][ar] = av.y;
            As[akq * 4 + 2][ar] = av.z;
            As[akq * 4 + 3][ar] = av.w;
            int bkr = f >> 5, bcq = f & 31;
            *(float4*)(&Bs[bkr][bcq * 4]) = *(const float4*)(B + (k0 + bkr) * 128 + bcq * 4);
        }
        __syncthreads();
#pragma unroll
        for (int kk = 0; kk < 16; kk++) {
            float ra[8], rb[8];
#pragma unroll
            for (int i = 0; i < 8; i++) ra[i] = As[kk][ty * 8 + i];
#pragma unroll
            for (int j = 0; j < 8; j++) rb[j] = Bs[kk][tx * 8 + j];
#pragma unroll
            for (int i = 0; i < 8; i++)
#pragma unroll
                for (int j = 0; j < 8; j++)
                    acc[i][j] = fmaf(ra[i], rb[j], acc[i][j]);
        }
        __syncthreads();
    }
#pragma unroll
    for (int i = 0; i < 8; i++) {
        int row = ty * 8 + i;
#pragma unroll
        for (int j = 0; j < 8; j++) {
            int col = tx * 8 + j;
            C[row * 128 + col] = acc[i][j] + A[row * 128 + col];
        }
    }
}

// ---------------- im2col (3x3, pad 1) into g_B: row = c*9 + kh*3 + kw ----------------
__global__ void im2col_k(const float* __restrict__ inp)
{
    int t = blockIdx.x * 256 + threadIdx.x;        // Cin*9*NPIX threads
    int pix = t & (NPIX - 1);
    int r = t >> 14;                               // c*9 + kk
    int kk = r % 9;
    int c  = r / 9;
    int kh = kk / 3, kw = kk % 3;
    int h = pix >> 7, w = pix & 127;
    int ih = h + kh - 1, iw = w + kw - 1;
    float v = 0.0f;
    if ((unsigned)ih < 128u && (unsigned)iw < 128u)
        v = inp[((size_t)c << 14) + (ih << 7) + iw];
    g_B[t] = v;
}

// ---------------- offsets conv as small-M GEMM: off(18xNPIX) = p_w(18x4608)@g_B + p_b ------
__global__ void __launch_bounds__(512) gemm_off(const float* __restrict__ A,
                                                const float* __restrict__ bias)
{
    const int K = 4608, KG = 1152;
    __shared__ float Ash[4][16][18];
    __shared__ float red[4][18][128];
    int tid  = threadIdx.x;
    int g    = tid >> 7;            // k-group 0..3
    int lane = tid & 127;
    int pix  = blockIdx.x * 128 + lane;

    float acc[18];
#pragma unroll
    for (int o = 0; o < 18; o++) acc[o] = 0.0f;

    for (int kc = 0; kc < KG; kc += 16) {
        int k0 = g * KG + kc;
        for (int i = lane; i < 288; i += 128) {
            int o = i / 16, kk = i % 16;
            Ash[g][kk][o] = A[o * K + k0 + kk];
        }
        __syncthreads();
#pragma unroll 4
        for (int kk = 0; kk < 16; kk++) {
            float b = g_B[(size_t)(k0 + kk) * NPIX + pix];
#pragma unroll
            for (int o = 0; o < 18; o++) acc[o] = fmaf(Ash[g][kk][o], b, acc[o]);
        }
        __syncthreads();
    }
#pragma unroll
    for (int o = 0; o < 18; o++) red[g][o][lane] = acc[o];
    __syncthreads();
    if (g == 0) {
#pragma unroll
        for (int o = 0; o < 18; o++) {
            float s = red[0][o][lane] + red[1][o][lane] + red[2][o][lane] + red[3][o][lane]
                    + bias[o];
            g_off[o * NPIX + pix] = s;
        }
    }
}

// ---------------- zero-pad cc -> ccp (512 x 130 x 130) ----------------
__global__ void pad_k()
{
    int t = blockIdx.x * 256 + threadIdx.x;
    if (t >= 512 * 16900) return;
    int c = t / 16900;
    int r = t % 16900;
    int i = r / 130, j = r % 130;
    float v = 0.0f;
    if (i >= 1 && i <= 128 && j >= 1 && j <= 128)
        v = g_cc[((size_t)c << 14) + ((i - 1) << 7) + (j - 1)];
    g_ccp[t] = v;
}

// ---------------- deform sampling coords + bilinear weights (exact reference semantics) ----
__global__ void coords_k()
{
    int t = blockIdx.x * 256 + threadIdx.x;        // 9*NPIX, layout [k][pix]
    int pix = t & (NPIX - 1);
    int k   = t >> 14;
    int h = pix >> 7, w = pix & 127;
    float pnx = (float)(k / 3 - 1);
    float pny = (float)(k % 3 - 1);
    float px = g_off[k * NPIX + pix]       + pnx + (float)(h + 1);
    float py = g_off[(9 + k) * NPIX + pix] + pny + (float)(w + 1);
    float fx = floorf(px), fy = floorf(py);
    float x0 = fminf(fmaxf(fx,        0.0f), 129.0f);
    float x1 = fminf(fmaxf(fx + 1.0f, 0.0f), 129.0f);
    float y0 = fminf(fmaxf(fy,        0.0f), 129.0f);
    float y1 = fminf(fmaxf(fy + 1.0f, 0.0f), 129.0f);
    float pxc = fminf(fmaxf(px, 0.0f), 129.0f);
    float pyc = fminf(fmaxf(py, 0.0f), 129.0f);
    float glt = (1.0f + (x0 - pxc)) * (1.0f + (y0 - pyc));
    float grb = (1.0f - (x1 - pxc)) * (1.0f - (y1 - pyc));
    float glb = (1.0f + (x0 - pxc)) * (1.0f - (y1 - pyc));
    float grt = (1.0f - (x1 - pxc)) * (1.0f + (y0 - pyc));
    int ix0 = (int)x0, ix1 = (int)x1, iy0 = (int)y0, iy1 = (int)y1;
    g_idx[t] = make_int4(ix0 * 130 + iy0, ix1 * 130 + iy1, ix0 * 130 + iy1, ix1 * 130 + iy0);
    g_wt[t]  = make_float4(glt, grb, glb, grt);
}

// ---------------- gather sampled values into g_B: row = c*9 + k ----------------
__global__ void deform_gather()
{
    int k   = blockIdx.y;                          // 0..8
    int pix = blockIdx.x * 128 + threadIdx.x;
    int4   id = g_idx[k * NPIX + pix];
    float4 w  = g_wt [k * NPIX + pix];
#pragma unroll 4
    for (int c = 0; c < 512; c++) {
        const float* p = g_ccp + (size_t)c * 16900;
        float v = w.x * p[id.x] + w.y * p[id.y] + w.z * p[id.z] + w.w * p[id.w];
        g_B[((size_t)c * 9 + k) * NPIX + pix] = v;
    }
}

// ---------------- host launcher ----------------
extern "C" void kernel_launch(void* const* d_in, const int* in_sizes, int n_in,
                              void* d_out, int out_size)
{
    (void)in_sizes; (void)n_in; (void)out_size;
    const float* x    = (const float*)d_in[0];
    const float* llf  = (const float*)d_in[1];
    const float* fm_w = (const float*)d_in[2];
    const float* fs_w = (const float*)d_in[3];
    const float* p_w  = (const float*)d_in[4];
    const float* p_b  = (const float*)d_in[5];
    const float* dc_w = (const float*)d_in[6];
    const float* lc1w = (const float*)d_in[7];
    const float* g1 = (const float*)d_in[8],  *b1 = (const float*)d_in[9];
    const float* m1 = (const float*)d_in[10], *v1 = (const float*)d_in[11];
    const float* lc2w = (const float*)d_in[12];
    const float* g2 = (const float*)d_in[13], *b2 = (const float*)d_in[14];
    const float* m2 = (const float*)d_in[15], *v2 = (const float*)d_in[16];
    float* out = (float*)d_out;

    float *cc, *vv, *uu, *Bb, *fam, *bns, *bnb;
    cudaGetSymbolAddress((void**)&cc,  g_cc);
    cudaGetSymbolAddress((void**)&vv,  g_v);
    cudaGetSymbolAddress((void**)&uu,  g_u);
    cudaGetSymbolAddress((void**)&Bb,  g_B);
    cudaGetSymbolAddress((void**)&fam, g_fam);
    cudaGetSymbolAddress((void**)&bns, g_bnscale);
    cudaGetSymbolAddress((void**)&bnb, g_bnbias);

    // 1. BN coefficients
    bncoef_k<<<1, 512>>>(g1, b1, m1, v1, g2, b2, m2, v2);
    // 2. xu -> cc[0:256]
    upsample_k<<<NPIX, 256>>>(x);
    // 3. v = sigmoid(fm_w @ llf)
    sgemm_epi<1><<<dim3(128, 2), 256>>>(fm_w, llf, vv, 256, nullptr, nullptr);
    // 4. u[c] = llf[c] @ v[c] + llf[c]
    chan_matmul<<<256, 256>>>(llf);
    // 5. Cf = fs_w @ u  -> cc[256:512]
    sgemm_epi<0><<<dim3(128, 2), 256>>>(fs_w, uu, cc + (size_t)256 * NPIX, 256, nullptr, nullptr);
    // 6. im2col(cc, 512ch) -> g_B
    im2col_k<<<512 * 9 * (NPIX / 256), 256>>>(cc);
    // 7. offsets = p_w @ g_B + p_b
    gemm_off<<<NPIX / 128, 512>>>(p_w, p_b);
    // 8. pad cc -> ccp
    pad_k<<<(512 * 16900 + 255) / 256, 256>>>();
    // 9. per-(pixel,k) bilinear coords/weights
    coords_k<<<9 * NPIX / 256, 256>>>();
    // 10. gather sampled maps -> g_B (4608 x NPIX)
    deform_gather<<<dim3(NPIX / 128, 9), 128>>>();
    // 11. fam = dc_w @ g_B + Cf
    sgemm_epi<2><<<dim3(128, 2), 256>>>(dc_w, Bb, fam, 4608, cc + (size_t)256 * NPIX, nullptr);
    // 12. im2col(fam) -> g_B
    im2col_k<<<256 * 9 * (NPIX / 256), 256>>>(fam);
    // 13. up1 = relu(bn1(lc1 @ g_B)) -> out[0 : 256*NPIX]
    sgemm_epi<3><<<dim3(128, 2), 256>>>(lc1w, Bb, out, 2304, bns, bnb);
    // 14. im2col(up1) -> g_B
    im2col_k<<<256 * 9 * (NPIX / 256), 256>>>(out);
    // 15. up2 = relu(bn2(lc2 @ g_B)) -> out[256*NPIX : ]
    sgemm_epi<3><<<dim3(128, 2), 256>>>(lc2w, Bb, out + (size_t)256 * NPIX, 2304,
                                        bns + 256, bnb + 256);
}

// round 3
// speedup vs baseline: 1.7847x; 1.7847x over previous
#include <cuda_runtime.h>
#include <cuda_bf16.h>
#include <math.h>
#include <stdint.h>

#define NPIX 16384          // 128*128

// ---------------- static device scratch (no allocations allowed) ----------------
__device__ __align__(16) float  g_cc [512 * NPIX];           // [xu(256) ; Cf(256)]
__device__ __align__(16) float  g_ccp[512 * 130 * 130];      // zero-padded cc
__device__ __align__(16) float  g_v  [256 * NPIX];
__device__ __align__(16) float  g_u  [256 * NPIX];
__device__ __align__(16) float  g_off[ 18 * NPIX];
__device__ __align__(16) int4   g_idx[9 * NPIX];
__device__ __align__(16) float4 g_wt [9 * NPIX];
__device__ __align__(16) float  g_fam[256 * NPIX];
__device__ __align__(16) float  g_bnscale[512];
__device__ __align__(16) float  g_bnbias [512];
// bf16 hi/lo B planes, layout Bt[n][k] (K-major rows), max K = 4608
__device__ __align__(16) __nv_bfloat16 g_Bh[(size_t)NPIX * 4608];
__device__ __align__(16) __nv_bfloat16 g_Bl[(size_t)NPIX * 4608];
// bf16 hi/lo weight planes: dc(256x4608) @0, lc1(256x2304) @1179648, lc2 @1769472
__device__ __align__(16) __nv_bfloat16 g_Ah[2359296];
__device__ __align__(16) __nv_bfloat16 g_Al[2359296];

// ---------------- PTX helpers (all valid at compute_103 baseline target) ----------------
__device__ __forceinline__ uint32_t smem_u32(const void* p) {
    uint32_t a;
    asm("{ .reg .u64 t; cvta.to.shared.u64 t, %1; cvt.u32.u64 %0, t; }" : "=r"(a) : "l"(p));
    return a;
}
#define CP_ASYNC16(dst, src) \
    asm volatile("cp.async.cg.shared.global [%0], [%1], 16;" :: "r"(dst), "l"(src))
#define CP_COMMIT() asm volatile("cp.async.commit_group;")
#define CP_WAIT1()  asm volatile("cp.async.wait_group 1;" ::: "memory")
#define CP_WAIT0()  asm volatile("cp.async.wait_group 0;" ::: "memory")

__device__ __forceinline__ void ldsm4(uint32_t r[4], uint32_t addr) {
    asm volatile("ldmatrix.sync.aligned.m8n8.x4.shared.b16 {%0,%1,%2,%3}, [%4];"
                 : "=r"(r[0]), "=r"(r[1]), "=r"(r[2]), "=r"(r[3]) : "r"(addr));
}
__device__ __forceinline__ void mma_bf16(float c[4], const uint32_t a[4],
                                         uint32_t b0, uint32_t b1) {
    asm volatile("mma.sync.aligned.m16n8k16.row.col.f32.bf16.bf16.f32 "
                 "{%0,%1,%2,%3}, {%4,%5,%6,%7}, {%8,%9}, {%0,%1,%2,%3};"
                 : "+f"(c[0]), "+f"(c[1]), "+f"(c[2]), "+f"(c[3])
                 : "r"(a[0]), "r"(a[1]), "r"(a[2]), "r"(a[3]), "r"(b0), "r"(b1));
}

// ---------------- BN coefficient precompute ----------------
__global__ void bncoef_k(const float* __restrict__ g1, const float* __restrict__ b1,
                         const float* __restrict__ m1, const float* __restrict__ v1,
                         const float* __restrict__ g2, const float* __restrict__ b2,
                         const float* __restrict__ m2, const float* __restrict__ v2)
{
    int i = threadIdx.x;
    if (i < 256) {
        float s = g1[i] / sqrtf(v1[i] + 1e-5f);
        g_bnscale[i] = s;
        g_bnbias[i]  = b1[i] - m1[i] * s;
    } else {
        int j = i - 256;
        float s = g2[j] / sqrtf(v2[j] + 1e-5f);
        g_bnscale[i] = s;
        g_bnbias[i]  = b2[j] - m2[j] * s;
    }
}

// ---------------- weight hi/lo split ----------------
__global__ void split_w(const float* __restrict__ w, __nv_bfloat16* __restrict__ hi,
                        __nv_bfloat16* __restrict__ lo, int n)
{
    int t = blockIdx.x * 256 + threadIdx.x;
    if (t < n) {
        float v = w[t];
        __nv_bfloat16 h = __float2bfloat16(v);
        hi[t] = h;
        lo[t] = __float2bfloat16(v - __bfloat162float(h));
    }
}

// ---------------- bilinear upsample 32x32 -> 128x128, align_corners=True ----------------
__global__ void upsample_k(const float* __restrict__ x)
{
    int t = blockIdx.x * 256 + threadIdx.x;
    int pix = t & (NPIX - 1);
    int c   = t >> 14;
    int oy = pix >> 7, ox = pix & 127;
    const float s = 31.0f / 127.0f;
    float fy = oy * s, fx = ox * s;
    int y0 = (int)floorf(fy); int y1 = min(y0 + 1, 31);
    int x0 = (int)floorf(fx); int x1 = min(x0 + 1, 31);
    float wy = fy - (float)y0;
    float wx = fx - (float)x0;
    const float* xc = x + c * 1024;
    float v00 = xc[y0 * 32 + x0], v01 = xc[y0 * 32 + x1];
    float v10 = xc[y1 * 32 + x0], v11 = xc[y1 * 32 + x1];
    float r0 = v00 * (1.0f - wy) + v10 * wy;
    float r1 = v01 * (1.0f - wy) + v11 * wy;
    g_cc[t] = r0 * (1.0f - wx) + r1 * wx;
}

// ---------------- FFMA SGEMM for the two small K=256 GEMMs ----------------
// EPI: 0 none, 1 sigmoid
template<int EPI>
__global__ void __launch_bounds__(256, 2) sgemm_epi(
    const float* __restrict__ A, const float* __restrict__ B, float* __restrict__ C, int K)
{
    __shared__ float As[16][128];
    __shared__ float Bs[16][128];
    const int tid  = threadIdx.x;
    const int brow = blockIdx.y * 128;
    const int bcol = blockIdx.x * 128;
    const int ty = tid >> 4, tx = tid & 15;

    float acc[8][8];
#pragma unroll
    for (int i = 0; i < 8; i++)
#pragma unroll
        for (int j = 0; j < 8; j++) acc[i][j] = 0.0f;

    for (int k0 = 0; k0 < K; k0 += 16) {
#pragma unroll
        for (int l = 0; l < 2; l++) {
            int f = tid + l * 256;
            int ar = f >> 2, akq = f & 3;
            float4 av = *(const float4*)(A + (size_t)(brow + ar) * K + k0 + akq * 4);
            As[akq * 4 + 0][ar] = av.x;
            As[akq * 4 + 1][ar] = av.y;
            As[akq * 4 + 2][ar] = av.z;
            As[akq * 4 + 3][ar] = av.w;
            int bkr = f >> 5, bcq = f & 31;
            *(float4*)(&Bs[bkr][bcq * 4]) =
                *(const float4*)(B + (size_t)(k0 + bkr) * NPIX + bcol + bcq * 4);
        }
        __syncthreads();
#pragma unroll
        for (int kk = 0; kk < 16; kk++) {
            float ra[8], rb[8];
#pragma unroll
            for (int i = 0; i < 8; i++) ra[i] = As[kk][ty * 8 + i];
#pragma unroll
            for (int j = 0; j < 8; j++) rb[j] = Bs[kk][tx * 8 + j];
#pragma unroll
            for (int i = 0; i < 8; i++)
#pragma unroll
                for (int j = 0; j < 8; j++)
                    acc[i][j] = fmaf(ra[i], rb[j], acc[i][j]);
        }
        __syncthreads();
    }
#pragma unroll
    for (int i = 0; i < 8; i++) {
        int row = brow + ty * 8 + i;
#pragma unroll
        for (int j = 0; j < 8; j++) {
            int col = bcol + tx * 8 + j;
            float v = acc[i][j];
            if (EPI == 1) v = 1.0f / (1.0f + expf(-v));
            C[(size_t)row * NPIX + col] = v;
        }
    }
}

// ---------------- per-channel 128x128x128 matmul: u[c] = llf[c] @ v[c] + llf[c] ----------------
__global__ void __launch_bounds__(256, 2) chan_matmul(const float* __restrict__ llf)
{
    const int c = blockIdx.x;
    const float* A = llf + (size_t)c * NPIX;
    const float* B = g_v + (size_t)c * NPIX;
    float*       C = g_u + (size_t)c * NPIX;

    __shared__ float As[16][128];
    __shared__ float Bs[16][128];
    const int tid = threadIdx.x;
    const int ty = tid >> 4, tx = tid & 15;

    float acc[8][8];
#pragma unroll
    for (int i = 0; i < 8; i++)
#pragma unroll
        for (int j = 0; j < 8; j++) acc[i][j] = 0.0f;

    for (int k0 = 0; k0 < 128; k0 += 16) {
#pragma unroll
        for (int l = 0; l < 2; l++) {
            int f = tid + l * 256;
            int ar = f >> 2, akq = f & 3;
            float4 av = *(const float4*)(A + ar * 128 + k0 + akq * 4);
            As[akq * 4 + 0][ar] = av.x;
            As[akq * 4 + 1][ar] = av.y;
            As[akq * 4 + 2][ar] = av.z;
            As[akq * 4 + 3][ar] = av.w;
            int bkr = f >> 5, bcq = f & 31;
            *(float4*)(&Bs[bkr][bcq * 4]) = *(const float4*)(B + (k0 + bkr) * 128 + bcq * 4);
        }
        __syncthreads();
#pragma unroll
        for (int kk = 0; kk < 16; kk++) {
            float ra[8], rb[8];
#pragma unroll
            for (int i = 0; i < 8; i++) ra[i] = As[kk][ty * 8 + i];
#pragma unroll
            for (int j = 0; j < 8; j++) rb[j] = Bs[kk][tx * 8 + j];
#pragma unroll
            for (int i = 0; i < 8; i++)
#pragma unroll
                for (int j = 0; j < 8; j++)
                    acc[i][j] = fmaf(ra[i], rb[j], acc[i][j]);
        }
        __syncthreads();
    }
#pragma unroll
    for (int i = 0; i < 8; i++) {
        int row = ty * 8 + i;
#pragma unroll
        for (int j = 0; j < 8; j++) {
            int col = tx * 8 + j;
            C[row * 128 + col] = acc[i][j] + A[row * 128 + col];
        }
    }
}

// ---------------- offsets conv (implicit im2col): off = p_w(18x4608) @ im2col(cc) + p_b ----
__global__ void __launch_bounds__(512) gemm_off(const float* __restrict__ A,
                                                const float* __restrict__ bias)
{
    const int K = 4608, KG = 1152;
    __shared__ float Ash[4][16][18];
    __shared__ float red[4][18][128];
    int tid  = threadIdx.x;
    int g    = tid >> 7;
    int lane = tid & 127;
    int pix  = blockIdx.x * 128 + lane;
    int h = pix >> 7, w = pix & 127;

    float acc[18];
#pragma unroll
    for (int o = 0; o < 18; o++) acc[o] = 0.0f;

    for (int kc = 0; kc < KG; kc += 16) {
        int k0 = g * KG + kc;
        for (int i = lane; i < 288; i += 128) {
            int o = i / 16, kk = i % 16;
            Ash[g][kk][o] = A[o * K + k0 + kk];
        }
        __syncthreads();
#pragma unroll 4
        for (int kk = 0; kk < 16; kk++) {
            int k = k0 + kk;
            int c = k / 9, r = k - c * 9;
            int kh = r / 3, kw = r - kh * 3;
            int ih = h + kh - 1, iw = w + kw - 1;
            float b = 0.0f;
            if ((unsigned)ih < 128u && (unsigned)iw < 128u)
                b = g_cc[((size_t)c << 14) + (ih << 7) + iw];
#pragma unroll
            for (int o = 0; o < 18; o++) acc[o] = fmaf(Ash[g][kk][o], b, acc[o]);
        }
        __syncthreads();
    }
#pragma unroll
    for (int o = 0; o < 18; o++) red[g][o][lane] = acc[o];
    __syncthreads();
    if (g == 0) {
#pragma unroll
        for (int o = 0; o < 18; o++) {
            float s = red[0][o][lane] + red[1][o][lane] + red[2][o][lane] + red[3][o][lane]
                    + bias[o];
            g_off[o * NPIX + pix] = s;
        }
    }
}

// ---------------- zero-pad cc -> ccp (512 x 130 x 130) ----------------
__global__ void pad_k()
{
    int t = blockIdx.x * 256 + threadIdx.x;
    if (t >= 512 * 16900) return;
    int c = t / 16900;
    int r = t % 16900;
    int i = r / 130, j = r % 130;
    float v = 0.0f;
    if (i >= 1 && i <= 128 && j >= 1 && j <= 128)
        v = g_cc[((size_t)c << 14) + ((i - 1) << 7) + (j - 1)];
    g_ccp[t] = v;
}

// ---------------- deform sampling coords + bilinear weights ----------------
__global__ void coords_k()
{
    int t = blockIdx.x * 256 + threadIdx.x;        // 9*NPIX, layout [k][pix]
    int pix = t & (NPIX - 1);
    int k   = t >> 14;
    int h = pix >> 7, w = pix & 127;
    float pnx = (float)(k / 3 - 1);
    float pny = (float)(k % 3 - 1);
    float px = g_off[k * NPIX + pix]       + pnx + (float)(h + 1);
    float py = g_off[(9 + k) * NPIX + pix] + pny + (float)(w + 1);
    float fx = floorf(px), fy = floorf(py);
    float x0 = fminf(fmaxf(fx,        0.0f), 129.0f);
    float x1 = fminf(fmaxf(fx + 1.0f, 0.0f), 129.0f);
    float y0 = fminf(fmaxf(fy,        0.0f), 129.0f);
    float y1 = fminf(fmaxf(fy + 1.0f, 0.0f), 129.0f);
    float pxc = fminf(fmaxf(px, 0.0f), 129.0f);
    float pyc = fminf(fmaxf(py, 0.0f), 129.0f);
    float glt = (1.0f + (x0 - pxc)) * (1.0f + (y0 - pyc));
    float grb = (1.0f - (x1 - pxc)) * (1.0f - (y1 - pyc));
    float glb = (1.0f + (x0 - pxc)) * (1.0f - (y1 - pyc));
    float grt = (1.0f - (x1 - pxc)) * (1.0f + (y0 - pyc));
    int ix0 = (int)x0, ix1 = (int)x1, iy0 = (int)y0, iy1 = (int)y1;
    g_idx[t] = make_int4(ix0 * 130 + iy0, ix1 * 130 + iy1, ix0 * 130 + iy1, ix1 * 130 + iy0);
    g_wt[t]  = make_float4(glt, grb, glb, grt);
}

// ---------------- deform gather -> bf16 hi/lo, layout Bt[n][k], k=c*9+kp ----------------
__global__ void __launch_bounds__(256) deform_gather_bf()
{
    __shared__ int4   sid[9][32];
    __shared__ float4 swt[9][32];
    __shared__ __nv_bfloat16 sh[32][132];
    __shared__ __nv_bfloat16 sl[32][132];
    int p0 = blockIdx.x * 32;
    int k0 = blockIdx.y * 128;
    int t = threadIdx.x;
    for (int i = t; i < 288; i += 256) {
        int kp = i >> 5, p = i & 31;
        sid[kp][p] = g_idx[kp * NPIX + p0 + p];
        swt[kp][p] = g_wt [kp * NPIX + p0 + p];
    }
    __syncthreads();
#pragma unroll
    for (int j = 0; j < 16; j++) {
        int s = j * 256 + t;               // 0..4095
        int p = s & 31, kl = s >> 5;
        int k = k0 + kl;
        int c = k / 9, kp = k - c * 9;
        const float* base = g_ccp + (size_t)c * 16900;
        int4   id = sid[kp][p];
        float4 w  = swt[kp][p];
        float v = w.x * base[id.x] + w.y * base[id.y] + w.z * base[id.z] + w.w * base[id.w];
        __nv_bfloat16 h = __float2bfloat16(v);
        sh[p][kl] = h;
        sl[p][kl] = __float2bfloat16(v - __bfloat162float(h));
    }
    __syncthreads();
    int p = t >> 3, sg = t & 7;
    size_t ob = (size_t)(p0 + p) * 4608 + k0;
#pragma unroll
    for (int q = 0; q < 4; q++) {
        int off = (q * 8 + sg) * 4;        // bf16 elems, 8-byte chunks
        *(uint2*)(g_Bh + ob + off) = *(uint2*)(&sh[p][off]);
        *(uint2*)(g_Bl + ob + off) = *(uint2*)(&sl[p][off]);
    }
}

// ---------------- im2col (3x3, pad 1) -> bf16 hi/lo, layout Bt[n][k], Ktot=2304 ----------
__global__ void __launch_bounds__(256) im2col_bf(const float* __restrict__ inp)
{
    __shared__ __nv_bfloat16 sh[32][132];
    __shared__ __nv_bfloat16 sl[32][132];
    int p0 = blockIdx.x * 32;
    int k0 = blockIdx.y * 128;
    int t = threadIdx.x;
#pragma unroll
    for (int j = 0; j < 16; j++) {
        int s = j * 256 + t;
        int p = s & 31, kl = s >> 5;
        int k = k0 + kl;
        int c = k / 9, r = k - c * 9;
        int kh = r / 3, kw = r - kh * 3;
        int pix = p0 + p;
        int h = pix >> 7, w = pix & 127;
        int ih = h + kh - 1, iw = w + kw - 1;
        float v = 0.0f;
        if ((unsigned)ih < 128u && (unsigned)iw < 128u)
            v = inp[((size_t)c << 14) + (ih << 7) + iw];
        __nv_bfloat16 hh = __float2bfloat16(v);
        sh[p][kl] = hh;
        sl[p][kl] = __float2bfloat16(v - __bfloat162float(hh));
    }
    __syncthreads();
    int p = t >> 3, sg = t & 7;
    size_t ob = (size_t)(p0 + p) * 2304 + k0;
#pragma unroll
    for (int q = 0; q < 4; q++) {
        int off = (q * 8 + sg) * 4;
        *(uint2*)(g_Bh + ob + off) = *(uint2*)(&sh[p][off]);
        *(uint2*)(g_Bl + ob + off) = *(uint2*)(&sl[p][off]);
    }
}

// ---------------- HMMA bf16 split GEMM ----------------
// D[m][n] = sum_k (Ah+Al)[m][k]*(Bh+Bl)[n][k] via 3 terms, fp32 accum.
// Tile 128x128, BK=32, 8 warps (2x4), warp tile 64x32, m16n8k16 fragments.
// EPI 2: + e1 full map; EPI 3: relu(x*e1[row]+e2[row])
#define BK        32
#define ASTRIDE   40                       // bf16 elems per smem row (80B, conflict-free LDSM)
#define PLANE_B   (128 * ASTRIDE * 2)      // 10240 B
#define STAGE_B   (4 * PLANE_B)            // Ah, Al, Bh, Bl
#define GEMM_SMEM (2 * STAGE_B)            // 81920 B

__device__ __forceinline__ void issue_stage(
    uint32_t sb, int stage, const __nv_bfloat16* __restrict__ pA_h,
    const __nv_bfloat16* __restrict__ pA_l, const __nv_bfloat16* __restrict__ pB_h,
    const __nv_bfloat16* __restrict__ pB_l, int K, int k0, int tid)
{
    const __nv_bfloat16* srcs[4] = {pA_h, pA_l, pB_h, pB_l};
    uint32_t stb = sb + stage * STAGE_B;
#pragma unroll
    for (int pl = 0; pl < 4; pl++) {
#pragma unroll
        for (int q = 0; q < 2; q++) {
            int id  = tid * 2 + q;         // 0..511
            int row = id >> 2, seg = id & 3;
            uint32_t dst = stb + pl * PLANE_B + (row * ASTRIDE + seg * 8) * 2;
            const void* src = srcs[pl] + (size_t)row * K + k0 + seg * 8;
            CP_ASYNC16(dst, src);
        }
    }
    CP_COMMIT();
}

__global__ void __launch_bounds__(256, 1) mma_gemm(
    const __nv_bfloat16* __restrict__ Ah, const __nv_bfloat16* __restrict__ Al,
    const __nv_bfloat16* __restrict__ Bh, const __nv_bfloat16* __restrict__ Bl,
    float* __restrict__ C, int K, int EPI,
    const float* __restrict__ e1, const float* __restrict__ e2)
{
    extern __shared__ char sm[];
    uint32_t sb = smem_u32(sm);
    const int tid = threadIdx.x;
    const int wid = tid >> 5, lane = tid & 31;
    const int wr = wid >> 2, wc = wid & 3;          // warp grid 2x4
    const int brow = blockIdx.y * 128, bcol = blockIdx.x * 128;

    const __nv_bfloat16* pA_h = Ah + (size_t)brow * K;
    const __nv_bfloat16* pA_l = Al + (size_t)brow * K;
    const __nv_bfloat16* pB_h = Bh + (size_t)bcol * K;
    const __nv_bfloat16* pB_l = Bl + (size_t)bcol * K;

    float acc[4][4][4];
#pragma unroll
    for (int i = 0; i < 4; i++)
#pragma unroll
        for (int j = 0; j < 4; j++)
#pragma unroll
            for (int q = 0; q < 4; q++) acc[i][j][q] = 0.0f;

    // ldmatrix per-thread base offsets
    const int sub = lane >> 3, rr = lane & 7;
    // A: r0=(m+0,k+0) r1=(m+8,k+0) r2=(m+0,k+8) r3=(m+8,k+8)
    const int am = wr * 64 + (sub & 1) * 8 + rr;
    const int ak = (sub >> 1) * 8;
    // B: r0=(n+0,k+0) r1=(n+0,k+8) r2=(n+8,k+0) r3=(n+8,k+8)
    const int bn = wc * 32 + (sub >> 1) * 8 + rr;
    const int bk = (sub & 1) * 8;

    const int NC = K / BK;
    issue_stage(sb, 0, pA_h, pA_l, pB_h, pB_l, K, 0, tid);

    for (int ci = 0; ci < NC; ci++) {
        if (ci + 1 < NC) {
            issue_stage(sb, (ci + 1) & 1, pA_h, pA_l, pB_h, pB_l, K, (ci + 1) * BK, tid);
            CP_WAIT1();
        } else {
            CP_WAIT0();
        }
        __syncthreads();

        uint32_t stb = sb + (ci & 1) * STAGE_B;
#pragma unroll
        for (int ks = 0; ks < 2; ks++) {
            uint32_t ah[4][4], al[4][4], bh[4][2], bl[4][2];
#pragma unroll
            for (int mt = 0; mt < 4; mt++) {
                uint32_t aoff = ((am + mt * 16) * ASTRIDE + ks * 16 + ak) * 2;
                ldsm4(ah[mt], stb + aoff);
                ldsm4(al[mt], stb + PLANE_B + aoff);
            }
#pragma unroll
            for (int ntp = 0; ntp < 2; ntp++) {
                uint32_t boff = ((bn + ntp * 16) * ASTRIDE + ks * 16 + bk) * 2;
                uint32_t rh[4], rl[4];
                ldsm4(rh, stb + 2 * PLANE_B + boff);
                ldsm4(rl, stb + 3 * PLANE_B + boff);
                bh[ntp * 2 + 0][0] = rh[0]; bh[ntp * 2 + 0][1] = rh[1];
                bh[ntp * 2 + 1][0] = rh[2]; bh[ntp * 2 + 1][1] = rh[3];
                bl[ntp * 2 + 0][0] = rl[0]; bl[ntp * 2 + 0][1] = rl[1];
                bl[ntp * 2 + 1][0] = rl[2]; bl[ntp * 2 + 1][1] = rl[3];
            }
#pragma unroll
            for (int mt = 0; mt < 4; mt++)
#pragma unroll
                for (int nt = 0; nt < 4; nt++) {
                    mma_bf16(acc[mt][nt], ah[mt], bh[nt][0], bh[nt][1]);
                    mma_bf16(acc[mt][nt], al[mt], bh[nt][0], bh[nt][1]);
                    mma_bf16(acc[mt][nt], ah[mt], bl[nt][0], bl[nt][1]);
                }
        }
        __syncthreads();
    }

    // ---------------- epilogue ----------------
    const int gid = lane >> 2, t4 = lane & 3;
#pragma unroll
    for (int mt = 0; mt < 4; mt++) {
        int m0 = brow + wr * 64 + mt * 16 + gid;
#pragma unroll
        for (int nt = 0; nt < 4; nt++) {
            int n0 = bcol + wc * 32 + nt * 8 + t4 * 2;
            if (EPI == 2) {
                size_t o0 = (size_t)m0 * NPIX + n0;
                size_t o1 = (size_t)(m0 + 8) * NPIX + n0;
                float2 r0 = make_float2(acc[mt][nt][0] + e1[o0],
                                        acc[mt][nt][1] + e1[o0 + 1]);
                float2 r1 = make_float2(acc[mt][nt][2] + e1[o1],
                                        acc[mt][nt][3] + e1[o1 + 1]);
                *(float2*)(C + o0) = r0;
                *(float2*)(C + o1) = r1;
            } else {
                float s0 = e1[m0], b0 = e2[m0];
                float s1 = e1[m0 + 8], b1 = e2[m0 + 8];
                float v0 = fmaxf(acc[mt][nt][0] * s0 + b0, 0.0f);
                float v1 = fmaxf(acc[mt][nt][1] * s0 + b0, 0.0f);
                float v2 = fmaxf(acc[mt][nt][2] * s1 + b1, 0.0f);
                float v3 = fmaxf(acc[mt][nt][3] * s1 + b1, 0.0f);
                *(float2*)(C + (size_t)m0 * NPIX + n0)       = make_float2(v0, v1);
                *(float2*)(C + (size_t)(m0 + 8) * NPIX + n0) = make_float2(v2, v3);
            }
        }
    }
}

// ---------------- host launcher ----------------
extern "C" void kernel_launch(void* const* d_in, const int* in_sizes, int n_in,
                              void* d_out, int out_size)
{
    (void)in_sizes; (void)n_in; (void)out_size;
    const float* x    = (const float*)d_in[0];
    const float* llf  = (const float*)d_in[1];
    const float* fm_w = (const float*)d_in[2];
    const float* fs_w = (const float*)d_in[3];
    const float* p_w  = (const float*)d_in[4];
    const float* p_b  = (const float*)d_in[5];
    const float* dc_w = (const float*)d_in[6];
    const float* lc1w = (const float*)d_in[7];
    const float* g1 = (const float*)d_in[8],  *b1 = (const float*)d_in[9];
    const float* m1 = (const float*)d_in[10], *v1 = (const float*)d_in[11];
    const float* lc2w = (const float*)d_in[12];
    const float* g2 = (const float*)d_in[13], *b2 = (const float*)d_in[14];
    const float* m2 = (const float*)d_in[15], *v2 = (const float*)d_in[16];
    float* out = (float*)d_out;

    float *cc, *vv, *uu, *fam, *bns, *bnb;
    __nv_bfloat16 *Bh, *Bl, *Ah, *Al;
    cudaGetSymbolAddress((void**)&cc,  g_cc);
    cudaGetSymbolAddress((void**)&vv,  g_v);
    cudaGetSymbolAddress((void**)&uu,  g_u);
    cudaGetSymbolAddress((void**)&fam, g_fam);
    cudaGetSymbolAddress((void**)&bns, g_bnscale);
    cudaGetSymbolAddress((void**)&bnb, g_bnbias);
    cudaGetSymbolAddress((void**)&Bh,  g_Bh);
    cudaGetSymbolAddress((void**)&Bl,  g_Bl);
    cudaGetSymbolAddress((void**)&Ah,  g_Ah);
    cudaGetSymbolAddress((void**)&Al,  g_Al);

    cudaFuncSetAttribute(mma_gemm, cudaFuncAttributeMaxDynamicSharedMemorySize, GEMM_SMEM);

    // 1. BN coefficients + weight splits
    bncoef_k<<<1, 512>>>(g1, b1, m1, v1, g2, b2, m2, v2);
    split_w<<<(1179648 + 255) / 256, 256>>>(dc_w, Ah, Al, 1179648);
    split_w<<<(589824 + 255) / 256, 256>>>(lc1w, Ah + 1179648, Al + 1179648, 589824);
    split_w<<<(589824 + 255) / 256, 256>>>(lc2w, Ah + 1769472, Al + 1769472, 589824);
    // 2. xu -> cc[0:256]
    upsample_k<<<NPIX, 256>>>(x);
    // 3. v = sigmoid(fm_w @ llf)
    sgemm_epi<1><<<dim3(128, 2), 256>>>(fm_w, llf, vv, 256);
    // 4. u[c] = llf[c] @ v[c] + llf[c]
    chan_matmul<<<256, 256>>>(llf);
    // 5. Cf = fs_w @ u  -> cc[256:512]
    sgemm_epi<0><<<dim3(128, 2), 256>>>(fs_w, uu, cc + (size_t)256 * NPIX, 256);
    // 6. offsets = p_w @ im2col(cc) + p_b (implicit im2col)
    gemm_off<<<NPIX / 128, 512>>>(p_w, p_b);
    // 7. pad cc -> ccp
    pad_k<<<(512 * 16900 + 255) / 256, 256>>>();
    // 8. bilinear coords/weights
    coords_k<<<9 * NPIX / 256, 256>>>();
    // 9. gather samples -> Bt hi/lo [n][4608]
    deform_gather_bf<<<dim3(NPIX / 32, 36), 256>>>();
    // 10. fam = dc_w @ Bt + Cf   (HMMA)
    mma_gemm<<<dim3(128, 2), 256, GEMM_SMEM>>>(Ah, Al, Bh, Bl, fam, 4608, 2,
                                               cc + (size_t)256 * NPIX, nullptr);
    // 11. im2col(fam) -> Bt hi/lo [n][2304]
    im2col_bf<<<dim3(NPIX / 32, 18), 256>>>(fam);
    // 12. up1 = relu(bn1(lc1 @ Bt)) -> out[0:256*NPIX]   (HMMA)
    mma_gemm<<<dim3(128, 2), 256, GEMM_SMEM>>>(Ah + 1179648, Al + 1179648, Bh, Bl,
                                               out, 2304, 3, bns, bnb);
    // 13. im2col(up1) -> Bt
    im2col_bf<<<dim3(NPIX / 32, 18), 256>>>(out);
    // 14. up2 = relu(bn2(lc2 @ Bt)) -> out[256*NPIX:]   (HMMA)
    mma_gemm<<<dim3(128, 2), 256, GEMM_SMEM>>>(Ah + 1769472, Al + 1769472, Bh, Bl,
                                               out + (size_t)256 * NPIX, 2304, 3,
                                               bns + 256, bnb + 256);
}

// round 4
// speedup vs baseline: 2.0136x; 1.1283x over previous
#include <cuda_runtime.h>
#include <cuda_bf16.h>
#include <math.h>
#include <stdint.h>

#define NPIX 16384          // 128*128

// ---------------- static device scratch (no allocations allowed) ----------------
__device__ __align__(16) float  g_cc  [512 * NPIX];          // [xu(256) ; Cf(256)] chan-major
__device__ __align__(16) float  g_ccpT[130 * 130 * 512];     // padded, [q][c] chan-fastest
__device__ __align__(16) float  g_v   [256 * NPIX];          // v; later reused as up1T
__device__ __align__(16) float  g_u   [256 * NPIX];          // u; later reused as famT
__device__ __align__(16) float  g_off [ 18 * NPIX];
__device__ __align__(16) int4   g_idx [9 * NPIX];
__device__ __align__(16) float4 g_wt  [9 * NPIX];
__device__ __align__(16) float  g_bnscale[512];
__device__ __align__(16) float  g_bnbias [512];
// bf16 hi/lo B planes, layout Bt[n][k] (K-major rows), max K = 4608, k = kp*C + c
__device__ __align__(16) __nv_bfloat16 g_Bh[(size_t)NPIX * 4608];
__device__ __align__(16) __nv_bfloat16 g_Bl[(size_t)NPIX * 4608];
// bf16 hi/lo weight planes (k-permuted): dc @0, lc1 @1179648, lc2 @1769472
__device__ __align__(16) __nv_bfloat16 g_Ah[2359296];
__device__ __align__(16) __nv_bfloat16 g_Al[2359296];

// ---------------- PTX helpers (baseline compute_103 ISA only) ----------------
__device__ __forceinline__ uint32_t smem_u32(const void* p) {
    uint32_t a;
    asm("{ .reg .u64 t; cvta.to.shared.u64 t, %1; cvt.u32.u64 %0, t; }" : "=r"(a) : "l"(p));
    return a;
}
#define CP_ASYNC16(dst, src) \
    asm volatile("cp.async.cg.shared.global [%0], [%1], 16;" :: "r"(dst), "l"(src))
#define CP_COMMIT() asm volatile("cp.async.commit_group;")
#define CP_WAIT2()  asm volatile("cp.async.wait_group 2;" ::: "memory")
#define CP_WAIT1()  asm volatile("cp.async.wait_group 1;" ::: "memory")
#define CP_WAIT0()  asm volatile("cp.async.wait_group 0;" ::: "memory")

__device__ __forceinline__ void ldsm4(uint32_t r[4], uint32_t addr) {
    asm volatile("ldmatrix.sync.aligned.m8n8.x4.shared.b16 {%0,%1,%2,%3}, [%4];"
                 : "=r"(r[0]), "=r"(r[1]), "=r"(r[2]), "=r"(r[3]) : "r"(addr));
}
__device__ __forceinline__ void mma_bf16(float c[4], const uint32_t a[4],
                                         uint32_t b0, uint32_t b1) {
    asm volatile("mma.sync.aligned.m16n8k16.row.col.f32.bf16.bf16.f32 "
                 "{%0,%1,%2,%3}, {%4,%5,%6,%7}, {%8,%9}, {%0,%1,%2,%3};"
                 : "+f"(c[0]), "+f"(c[1]), "+f"(c[2]), "+f"(c[3])
                 : "r"(a[0]), "r"(a[1]), "r"(a[2]), "r"(a[3]), "r"(b0), "r"(b1));
}

// ---------------- BN coefficient precompute ----------------
__global__ void bncoef_k(const float* __restrict__ g1, const float* __restrict__ b1,
                         const float* __restrict__ m1, const float* __restrict__ v1,
                         const float* __restrict__ g2, const float* __restrict__ b2,
                         const float* __restrict__ m2, const float* __restrict__ v2)
{
    int i = threadIdx.x;
    if (i < 256) {
        float s = g1[i] / sqrtf(v1[i] + 1e-5f);
        g_bnscale[i] = s;
        g_bnbias[i]  = b1[i] - m1[i] * s;
    } else {
        int j = i - 256;
        float s = g2[j] / sqrtf(v2[j] + 1e-5f);
        g_bnscale[i] = s;
        g_bnbias[i]  = b2[j] - m2[j] * s;
    }
}

// ---------------- weight hi/lo split with K permutation: k = kp*C + c ----------------
__global__ void split_perm(const float* __restrict__ w, __nv_bfloat16* __restrict__ hi,
                           __nv_bfloat16* __restrict__ lo, int C, int n)
{
    int t = blockIdx.x * 256 + threadIdx.x;
    if (t >= n) return;
    int K = C * 9;
    int o = t / K, r = t - o * K;
    int c = r / 9, kp = r - c * 9;
    int dst = o * K + kp * C + c;
    float v = w[t];
    __nv_bfloat16 h = __float2bfloat16(v);
    hi[dst] = h;
    lo[dst] = __float2bfloat16(v - __bfloat162float(h));
}

// ---------------- bilinear upsample 32x32 -> 128x128, align_corners=True ----------------
__global__ void upsample_k(const float* __restrict__ x)
{
    int t = blockIdx.x * 256 + threadIdx.x;
    int pix = t & (NPIX - 1);
    int c   = t >> 14;
    int oy = pix >> 7, ox = pix & 127;
    const float s = 31.0f / 127.0f;
    float fy = oy * s, fx = ox * s;
    int y0 = (int)floorf(fy); int y1 = min(y0 + 1, 31);
    int x0 = (int)floorf(fx); int x1 = min(x0 + 1, 31);
    float wy = fy - (float)y0;
    float wx = fx - (float)x0;
    const float* xc = x + c * 1024;
    float v00 = xc[y0 * 32 + x0], v01 = xc[y0 * 32 + x1];
    float v10 = xc[y1 * 32 + x0], v11 = xc[y1 * 32 + x1];
    float r0 = v00 * (1.0f - wy) + v10 * wy;
    float r1 = v01 * (1.0f - wy) + v11 * wy;
    g_cc[t] = r0 * (1.0f - wx) + r1 * wx;
}

// ---------------- FFMA SGEMM for the two small K=256 GEMMs ----------------
template<int EPI>   // 0 none, 1 sigmoid
__global__ void __launch_bounds__(256, 2) sgemm_epi(
    const float* __restrict__ A, const float* __restrict__ B, float* __restrict__ C, int K)
{
    __shared__ float As[16][128];
    __shared__ float Bs[16][128];
    const int tid  = threadIdx.x;
    const int brow = blockIdx.y * 128;
    const int bcol = blockIdx.x * 128;
    const int ty = tid >> 4, tx = tid & 15;

    float acc[8][8];
#pragma unroll
    for (int i = 0; i < 8; i++)
#pragma unroll
        for (int j = 0; j < 8; j++) acc[i][j] = 0.0f;

    for (int k0 = 0; k0 < K; k0 += 16) {
#pragma unroll
        for (int l = 0; l < 2; l++) {
            int f = tid + l * 256;
            int ar = f >> 2, akq = f & 3;
            float4 av = *(const float4*)(A + (size_t)(brow + ar) * K + k0 + akq * 4);
            As[akq * 4 + 0][ar] = av.x;
            As[akq * 4 + 1][ar] = av.y;
            As[akq * 4 + 2][ar] = av.z;
            As[akq * 4 + 3][ar] = av.w;
            int bkr = f >> 5, bcq = f & 31;
            *(float4*)(&Bs[bkr][bcq * 4]) =
                *(const float4*)(B + (size_t)(k0 + bkr) * NPIX + bcol + bcq * 4);
        }
        __syncthreads();
#pragma unroll
        for (int kk = 0; kk < 16; kk++) {
            float ra[8], rb[8];
#pragma unroll
            for (int i = 0; i < 8; i++) ra[i] = As[kk][ty * 8 + i];
#pragma unroll
            for (int j = 0; j < 8; j++) rb[j] = Bs[kk][tx * 8 + j];
#pragma unroll
            for (int i = 0; i < 8; i++)
#pragma unroll
                for (int j = 0; j < 8; j++)
                    acc[i][j] = fmaf(ra[i], rb[j], acc[i][j]);
        }
        __syncthreads();
    }
#pragma unroll
    for (int i = 0; i < 8; i++) {
        int row = brow + ty * 8 + i;
#pragma unroll
        for (int j = 0; j < 8; j++) {
            int col = bcol + tx * 8 + j;
            float v = acc[i][j];
            if (EPI == 1) v = 1.0f / (1.0f + expf(-v));
            C[(size_t)row * NPIX + col] = v;
        }
    }
}

// ---------------- per-channel 128x128x128 matmul: u[c] = llf[c] @ v[c] + llf[c] ----------------
__global__ void __launch_bounds__(256, 2) chan_matmul(const float* __restrict__ llf)
{
    const int c = blockIdx.x;
    const float* A = llf + (size_t)c * NPIX;
    const float* B = g_v + (size_t)c * NPIX;
    float*       C = g_u + (size_t)c * NPIX;

    __shared__ float As[16][128];
    __shared__ float Bs[16][128];
    const int tid = threadIdx.x;
    const int ty = tid >> 4, tx = tid & 15;

    float acc[8][8];
#pragma unroll
    for (int i = 0; i < 8; i++)
#pragma unroll
        for (int j = 0; j < 8; j++) acc[i][j] = 0.0f;

    for (int k0 = 0; k0 < 128; k0 += 16) {
#pragma unroll
        for (int l = 0; l < 2; l++) {
            int f = tid + l * 256;
            int ar = f >> 2, akq = f & 3;
            float4 av = *(const float4*)(A + ar * 128 + k0 + akq * 4);
            As[akq * 4 + 0][ar] = av.x;
            As[akq * 4 + 1][ar] = av.y;
            As[akq * 4 + 2][ar] = av.z;
            As[akq * 4 + 3][ar] = av.w;
            int bkr = f >> 5, bcq = f & 31;
            *(float4*)(&Bs[bkr][bcq * 4]) = *(const float4*)(B + (k0 + bkr) * 128 + bcq * 4);
        }
        __syncthreads();
#pragma unroll
        for (int kk = 0; kk < 16; kk++) {
            float ra[8], rb[8];
#pragma unroll
            for (int i = 0; i < 8; i++) ra[i] = As[kk][ty * 8 + i];
#pragma unroll
            for (int j = 0; j < 8; j++) rb[j] = Bs[kk][tx * 8 + j];
#pragma unroll
            for (int i = 0; i < 8; i++)
#pragma unroll
                for (int j = 0; j < 8; j++)
                    acc[i][j] = fmaf(ra[i], rb[j], acc[i][j]);
        }
        __syncthreads();
    }
#pragma unroll
    for (int i = 0; i < 8; i++) {
        int row = ty * 8 + i;
#pragma unroll
        for (int j = 0; j < 8; j++) {
            int col = tx * 8 + j;
            C[row * 128 + col] = acc[i][j] + A[row * 128 + col];
        }
    }
}

// ---------------- offsets conv (implicit im2col): off = p_w(18x4608) @ im2col(cc) + p_b ----
__global__ void __launch_bounds__(512) gemm_off(const float* __restrict__ A,
                                                const float* __restrict__ bias)
{
    const int K = 4608, KG = 1152;
    __shared__ float Ash[4][16][18];
    __shared__ float red[4][18][128];
    int tid  = threadIdx.x;
    int g    = tid >> 7;
    int lane = tid & 127;
    int pix  = blockIdx.x * 128 + lane;
    int h = pix >> 7, w = pix & 127;

    float acc[18];
#pragma unroll
    for (int o = 0; o < 18; o++) acc[o] = 0.0f;

    for (int kc = 0; kc < KG; kc += 16) {
        int k0 = g * KG + kc;
        for (int i = lane; i < 288; i += 128) {
            int o = i / 16, kk = i % 16;
            Ash[g][kk][o] = A[o * K + k0 + kk];
        }
        __syncthreads();
#pragma unroll 4
        for (int kk = 0; kk < 16; kk++) {
            int k = k0 + kk;
            int c = k / 9, r = k - c * 9;
            int kh = r / 3, kw = r - kh * 3;
            int ih = h + kh - 1, iw = w + kw - 1;
            float b = 0.0f;
            if ((unsigned)ih < 128u && (unsigned)iw < 128u)
                b = g_cc[((size_t)c << 14) + (ih << 7) + iw];
#pragma unroll
            for (int o = 0; o < 18; o++) acc[o] = fmaf(Ash[g][kk][o], b, acc[o]);
        }
        __syncthreads();
    }
#pragma unroll
    for (int o = 0; o < 18; o++) red[g][o][lane] = acc[o];
    __syncthreads();
    if (g == 0) {
#pragma unroll
        for (int o = 0; o < 18; o++) {
            float s = red[0][o][lane] + red[1][o][lane] + red[2][o][lane] + red[3][o][lane]
                    + bias[o];
            g_off[o * NPIX + pix] = s;
        }
    }
}

// ---------------- zero border rows of ccpT ----------------
__global__ void border_zero_k()
{
    int t = blockIdx.x * 256 + threadIdx.x;       // 516 * 512
    if (t >= 516 * 512) return;
    int b = t >> 9, c = t & 511;
    int q;
    if (b < 130)       q = b;                      // top row
    else if (b < 260)  q = 129 * 130 + (b - 130);  // bottom row
    else {
        int r = b - 260;                           // 0..255 -> side cols of rows 1..128
        int hh = 1 + (r >> 1);
        int ww = (r & 1) ? 129 : 0;
        q = hh * 130 + ww;
    }
    g_ccpT[(size_t)q * 512 + c] = 0.0f;
}

// ---------------- tiled transpose+pad: cc[c][pix] -> ccpT[(h+1)*130+w+1][c] ----------------
__global__ void transpose_pad_k()
{
    __shared__ float sm[32][33];
    int h  = blockIdx.x;            // 0..127
    int w0 = blockIdx.y * 32;
    int c0 = blockIdx.z * 32;
    int tx = threadIdx.x, ty = threadIdx.y;   // 32 x 8
#pragma unroll
    for (int i = 0; i < 4; i++)
        sm[ty + 8 * i][tx] = g_cc[(size_t)(c0 + ty + 8 * i) * NPIX + h * 128 + w0 + tx];
    __syncthreads();
#pragma unroll
    for (int i = 0; i < 4; i++)
        g_ccpT[(size_t)((h + 1) * 130 + (w0 + ty + 8 * i + 1)) * 512 + c0 + tx] =
            sm[tx][ty + 8 * i];
}

// ---------------- deform sampling coords + bilinear weights ----------------
__global__ void coords_k()
{
    int t = blockIdx.x * 256 + threadIdx.x;        // 9*NPIX, layout [k][pix]
    int pix = t & (NPIX - 1);
    int k   = t >> 14;
    int h = pix >> 7, w = pix & 127;
    float pnx = (float)(k / 3 - 1);
    float pny = (float)(k % 3 - 1);
    float px = g_off[k * NPIX + pix]       + pnx + (float)(h + 1);
    float py = g_off[(9 + k) * NPIX + pix] + pny + (float)(w + 1);
    float fx = floorf(px), fy = floorf(py);
    float x0 = fminf(fmaxf(fx,        0.0f), 129.0f);
    float x1 = fminf(fmaxf(fx + 1.0f, 0.0f), 129.0f);
    float y0 = fminf(fmaxf(fy,        0.0f), 129.0f);
    float y1 = fminf(fmaxf(fy + 1.0f, 0.0f), 129.0f);
    float pxc = fminf(fmaxf(px, 0.0f), 129.0f);
    float pyc = fminf(fmaxf(py, 0.0f), 129.0f);
    float glt = (1.0f + (x0 - pxc)) * (1.0f + (y0 - pyc));
    float grb = (1.0f - (x1 - pxc)) * (1.0f - (y1 - pyc));
    float glb = (1.0f + (x0 - pxc)) * (1.0f - (y1 - pyc));
    float grt = (1.0f - (x1 - pxc)) * (1.0f + (y0 - pyc));
    int ix0 = (int)x0, ix1 = (int)x1, iy0 = (int)y0, iy1 = (int)y1;
    g_idx[t] = make_int4(ix0 * 130 + iy0, ix1 * 130 + iy1, ix0 * 130 + iy1, ix1 * 130 + iy0);
    g_wt[t]  = make_float4(glt, grb, glb, grt);
}

// ---------------- coalesced deform gather: Bt[pix][kp*512+c] hi/lo ----------------
__global__ void __launch_bounds__(256) gather2()
{
    int pix = blockIdx.x;
    int kp  = blockIdx.y;
    int t   = threadIdx.x;                   // 256 threads, each 1 float2 (2 channels)
    int4   id = g_idx[kp * NPIX + pix];
    float4 w  = g_wt [kp * NPIX + pix];
    const float2* r0 = (const float2*)(g_ccpT + (size_t)id.x * 512);
    const float2* r1 = (const float2*)(g_ccpT + (size_t)id.y * 512);
    const float2* r2 = (const float2*)(g_ccpT + (size_t)id.z * 512);
    const float2* r3 = (const float2*)(g_ccpT + (size_t)id.w * 512);
    size_t ob = (size_t)pix * 4608 + kp * 512;
    float2 a = r0[t], b = r1[t], c = r2[t], d = r3[t];
    float v0 = w.x * a.x + w.y * b.x + w.z * c.x + w.w * d.x;
    float v1 = w.x * a.y + w.y * b.y + w.z * c.y + w.w * d.y;
    __nv_bfloat16 h0 = __float2bfloat16(v0);
    __nv_bfloat16 h1 = __float2bfloat16(v1);
    __nv_bfloat162 hp; hp.x = h0; hp.y = h1;
    __nv_bfloat162 lp;
    lp.x = __float2bfloat16(v0 - __bfloat162float(h0));
    lp.y = __float2bfloat16(v1 - __bfloat162float(h1));
    *(__nv_bfloat162*)(g_Bh + ob + 2 * t) = hp;
    *(__nv_bfloat162*)(g_Bl + ob + 2 * t) = lp;
}

// ---------------- coalesced im2col from transposed activation T[pix][256] ----------------
// Bt[pix][kp*256+c] = T[neighbor(pix,kp)][c] or 0 (pad)
__global__ void __launch_bounds__(256) im2colT(const float* __restrict__ T)
{
    int pix = blockIdx.x;
    int c   = threadIdx.x;
    int h = pix >> 7, w = pix & 127;
    size_t ob = (size_t)pix * 2304;
#pragma unroll
    for (int kp = 0; kp < 9; kp++) {
        int kh = kp / 3, kw = kp - kh * 3;
        int ih = h + kh - 1, iw = w + kw - 1;
        float v = 0.0f;
        if ((unsigned)ih < 128u && (unsigned)iw < 128u)
            v = T[(size_t)(ih * 128 + iw) * 256 + c];
        __nv_bfloat16 hh = __float2bfloat16(v);
        g_Bh[ob + kp * 256 + c] = hh;
        g_Bl[ob + kp * 256 + c] = __float2bfloat16(v - __bfloat162float(hh));
    }
}

// ---------------- HMMA bf16 split GEMM ----------------
// D[m][n] = sum_k (Ah+Al)[m][k]*(Bh+Bl)[n][k] via 3 terms, fp32 accum.
// Tile 128x128, BK=32, 3-stage cp.async pipeline, 8 warps (2x4), warp tile 64x32.
// EPI 2: (+e1 map) -> transposed store Ct[n][256] only
// EPI 3: relu(x*e1[row]+e2[row]) -> normal store C[m][NPIX]
// EPI 4: EPI3 normal store + transposed store Ct
#define BK        32
#define ASTRIDE   40                       // bf16 per smem row (80B, conflict-free LDSM)
#define PLANE_B   (128 * ASTRIDE * 2)      // 10240 B
#define STAGE_B   (4 * PLANE_B)            // Ah, Al, Bh, Bl = 40960 B
#define GEMM_SMEM (3 * STAGE_B)            // 122880 B

__device__ __forceinline__ void issue_stage(
    uint32_t sb, int stage, const __nv_bfloat16* __restrict__ pA_h,
    const __nv_bfloat16* __restrict__ pA_l, const __nv_bfloat16* __restrict__ pB_h,
    const __nv_bfloat16* __restrict__ pB_l, int K, int k0, int tid)
{
    const __nv_bfloat16* srcs[4] = {pA_h, pA_l, pB_h, pB_l};
    uint32_t stb = sb + stage * STAGE_B;
#pragma unroll
    for (int pl = 0; pl < 4; pl++) {
#pragma unroll
        for (int q = 0; q < 2; q++) {
            int id  = tid * 2 + q;         // 0..511
            int row = id >> 2, seg = id & 3;
            uint32_t dst = stb + pl * PLANE_B + (row * ASTRIDE + seg * 8) * 2;
            const void* src = srcs[pl] + (size_t)row * K + k0 + seg * 8;
            CP_ASYNC16(dst, src);
        }
    }
    CP_COMMIT();
}

template<int EPI>
__global__ void __launch_bounds__(256, 1) mma_gemm(
    const __nv_bfloat16* __restrict__ Ah, const __nv_bfloat16* __restrict__ Al,
    const __nv_bfloat16* __restrict__ Bh, const __nv_bfloat16* __restrict__ Bl,
    float* __restrict__ C, float* __restrict__ Ct, int K,
    const float* __restrict__ e1, const float* __restrict__ e2)
{
    extern __shared__ char sm[];
    uint32_t sb = smem_u32(sm);
    const int tid = threadIdx.x;
    const int wid = tid >> 5, lane = tid & 31;
    const int wr = wid >> 2, wc = wid & 3;          // warp grid 2x4
    const int brow = blockIdx.y * 128, bcol = blockIdx.x * 128;

    const __nv_bfloat16* pA_h = Ah + (size_t)brow * K;
    const __nv_bfloat16* pA_l = Al + (size_t)brow * K;
    const __nv_bfloat16* pB_h = Bh + (size_t)bcol * K;
    const __nv_bfloat16* pB_l = Bl + (size_t)bcol * K;

    float acc[4][4][4];
#pragma unroll
    for (int i = 0; i < 4; i++)
#pragma unroll
        for (int j = 0; j < 4; j++)
#pragma unroll
            for (int q = 0; q < 4; q++) acc[i][j][q] = 0.0f;

    const int sub = lane >> 3, rr = lane & 7;
    const int am = wr * 64 + (sub & 1) * 8 + rr;
    const int ak = (sub >> 1) * 8;
    const int bn = wc * 32 + (sub >> 1) * 8 + rr;
    const int bk = (sub & 1) * 8;

    const int NC = K / BK;
    issue_stage(sb, 0, pA_h, pA_l, pB_h, pB_l, K, 0, tid);
    issue_stage(sb, 1, pA_h, pA_l, pB_h, pB_l, K, BK, tid);

    for (int ci = 0; ci < NC; ci++) {
        if (ci + 2 < NC) {
            int s2 = (ci + 2) % 3;
            issue_stage(sb, s2, pA_h, pA_l, pB_h, pB_l, K, (ci + 2) * BK, tid);
            CP_WAIT2();
        } else if (ci + 1 < NC) {
            CP_WAIT1();
        } else {
            CP_WAIT0();
        }
        __syncthreads();

        uint32_t stb = sb + (ci % 3) * STAGE_B;
#pragma unroll
        for (int ks = 0; ks < 2; ks++) {
            uint32_t ah[4][4], al[4][4], bh[4][2], bl[4][2];
#pragma unroll
            for (int mt = 0; mt < 4; mt++) {
                uint32_t aoff = ((am + mt * 16) * ASTRIDE + ks * 16 + ak) * 2;
                ldsm4(ah[mt], stb + aoff);
                ldsm4(al[mt], stb + PLANE_B + aoff);
            }
#pragma unroll
            for (int ntp = 0; ntp < 2; ntp++) {
                uint32_t boff = ((bn + ntp * 16) * ASTRIDE + ks * 16 + bk) * 2;
                uint32_t rh[4], rl[4];
                ldsm4(rh, stb + 2 * PLANE_B + boff);
                ldsm4(rl, stb + 3 * PLANE_B + boff);
                bh[ntp * 2 + 0][0] = rh[0]; bh[ntp * 2 + 0][1] = rh[1];
                bh[ntp * 2 + 1][0] = rh[2]; bh[ntp * 2 + 1][1] = rh[3];
                bl[ntp * 2 + 0][0] = rl[0]; bl[ntp * 2 + 0][1] = rl[1];
                bl[ntp * 2 + 1][0] = rl[2]; bl[ntp * 2 + 1][1] = rl[3];
            }
#pragma unroll
            for (int mt = 0; mt < 4; mt++)
#pragma unroll
                for (int nt = 0; nt < 4; nt++) {
                    mma_bf16(acc[mt][nt], ah[mt], bh[nt][0], bh[nt][1]);
                    mma_bf16(acc[mt][nt], al[mt], bh[nt][0], bh[nt][1]);
                    mma_bf16(acc[mt][nt], ah[mt], bl[nt][0], bl[nt][1]);
                }
        }
        __syncthreads();
    }

    // ---------------- epilogue ----------------
    const int gid = lane >> 2, t4 = lane & 3;
    float* smf = (float*)sm;                        // reuse pipeline smem, stride 132
#pragma unroll
    for (int mt = 0; mt < 4; mt++) {
        int ml = wr * 64 + mt * 16 + gid;
        int m0 = brow + ml;
#pragma unroll
        for (int nt = 0; nt < 4; nt++) {
            int nl = wc * 32 + nt * 8 + t4 * 2;
            int n0 = bcol + nl;
            float v0, v1, v2, v3;
            if (EPI == 2) {
                size_t o0 = (size_t)m0 * NPIX + n0;
                size_t o1 = (size_t)(m0 + 8) * NPIX + n0;
                v0 = acc[mt][nt][0] + e1[o0];
                v1 = acc[mt][nt][1] + e1[o0 + 1];
                v2 = acc[mt][nt][2] + e1[o1];
                v3 = acc[mt][nt][3] + e1[o1 + 1];
            } else {
                float s0 = e1[m0], b0 = e2[m0];
                float s1 = e1[m0 + 8], b1 = e2[m0 + 8];
                v0 = fmaxf(acc[mt][nt][0] * s0 + b0, 0.0f);
                v1 = fmaxf(acc[mt][nt][1] * s0 + b0, 0.0f);
                v2 = fmaxf(acc[mt][nt][2] * s1 + b1, 0.0f);
                v3 = fmaxf(acc[mt][nt][3] * s1 + b1, 0.0f);
                *(float2*)(C + (size_t)m0 * NPIX + n0)       = make_float2(v0, v1);
                *(float2*)(C + (size_t)(m0 + 8) * NPIX + n0) = make_float2(v2, v3);
            }
            if (EPI == 2 || EPI == 4) {
                smf[(nl)     * 132 + ml]     = v0;
                smf[(nl + 1) * 132 + ml]     = v1;
                smf[(nl)     * 132 + ml + 8] = v2;
                smf[(nl + 1) * 132 + ml + 8] = v3;
            }
        }
    }
    if (EPI == 2 || EPI == 4) {
        __syncthreads();
#pragma unroll 4
        for (int i = 0; i < 64; i++) {
            int idx = i * 256 + tid;
            int nl = idx >> 7, ml = idx & 127;
            Ct[(size_t)(bcol + nl) * 256 + brow + ml] = smf[nl * 132 + ml];
        }
    }
}

// ---------------- host launcher ----------------
extern "C" void kernel_launch(void* const* d_in, const int* in_sizes, int n_in,
                              void* d_out, int out_size)
{
    (void)in_sizes; (void)n_in; (void)out_size;
    const float* x    = (const float*)d_in[0];
    const float* llf  = (const float*)d_in[1];
    const float* fm_w = (const float*)d_in[2];
    const float* fs_w = (const float*)d_in[3];
    const float* p_w  = (const float*)d_in[4];
    const float* p_b  = (const float*)d_in[5];
    const float* dc_w = (const float*)d_in[6];
    const float* lc1w = (const float*)d_in[7];
    const float* g1 = (const float*)d_in[8],  *b1 = (const float*)d_in[9];
    const float* m1 = (const float*)d_in[10], *v1 = (const float*)d_in[11];
    const float* lc2w = (const float*)d_in[12];
    const float* g2 = (const float*)d_in[13], *b2 = (const float*)d_in[14];
    const float* m2 = (const float*)d_in[15], *v2 = (const float*)d_in[16];
    float* out = (float*)d_out;

    float *cc, *vv, *uu, *bns, *bnb;
    __nv_bfloat16 *Bh, *Bl, *Ah, *Al;
    cudaGetSymbolAddress((void**)&cc,  g_cc);
    cudaGetSymbolAddress((void**)&vv,  g_v);
    cudaGetSymbolAddress((void**)&uu,  g_u);
    cudaGetSymbolAddress((void**)&bns, g_bnscale);
    cudaGetSymbolAddress((void**)&bnb, g_bnbias);
    cudaGetSymbolAddress((void**)&Bh,  g_Bh);
    cudaGetSymbolAddress((void**)&Bl,  g_Bl);
    cudaGetSymbolAddress((void**)&Ah,  g_Ah);
    cudaGetSymbolAddress((void**)&Al,  g_Al);

    cudaFuncSetAttribute(mma_gemm<2>, cudaFuncAttributeMaxDynamicSharedMemorySize, GEMM_SMEM);
    cudaFuncSetAttribute(mma_gemm<3>, cudaFuncAttributeMaxDynamicSharedMemorySize, GEMM_SMEM);
    cudaFuncSetAttribute(mma_gemm<4>, cudaFuncAttributeMaxDynamicSharedMemorySize, GEMM_SMEM);

    // 1. BN coefficients + permuted weight splits
    bncoef_k<<<1, 512>>>(g1, b1, m1, v1, g2, b2, m2, v2);
    split_perm<<<(1179648 + 255) / 256, 256>>>(dc_w, Ah, Al, 512, 1179648);
    split_perm<<<(589824 + 255) / 256, 256>>>(lc1w, Ah + 1179648, Al + 1179648, 256, 589824);
    split_perm<<<(589824 + 255) / 256, 256>>>(lc2w, Ah + 1769472, Al + 1769472, 256, 589824);
    // 2. xu -> cc[0:256]
    upsample_k<<<NPIX, 256>>>(x);
    // 3. v = sigmoid(fm_w @ llf)
    sgemm_epi<1><<<dim3(128, 2), 256>>>(fm_w, llf, vv, 256);
    // 4. u[c] = llf[c] @ v[c] + llf[c]
    chan_matmul<<<256, 256>>>(llf);
    // 5. Cf = fs_w @ u  -> cc[256:512]
    sgemm_epi<0><<<dim3(128, 2), 256>>>(fs_w, uu, cc + (size_t)256 * NPIX, 256);
    // 6. offsets = p_w @ im2col(cc) + p_b (implicit im2col)
    gemm_off<<<NPIX / 128, 512>>>(p_w, p_b);
    // 7. ccpT = pad+transpose(cc)
    border_zero_k<<<(516 * 512 + 255) / 256, 256>>>();
    transpose_pad_k<<<dim3(128, 4, 16), dim3(32, 8)>>>();
    // 8. bilinear coords/weights
    coords_k<<<9 * NPIX / 256, 256>>>();
    // 9. coalesced gather -> Bt hi/lo [pix][4608]
    gather2<<<dim3(NPIX, 9), 256>>>();
    // 10. famT = (dc_w @ Bt + Cf)^T -> g_u  (HMMA, transposed store)
    mma_gemm<2><<<dim3(128, 2), 256, GEMM_SMEM>>>(Ah, Al, Bh, Bl, nullptr, uu, 4608,
                                                  cc + (size_t)256 * NPIX, nullptr);
    // 11. im2col(famT) -> Bt hi/lo [pix][2304]
    im2colT<<<NPIX, 256>>>(uu);
    // 12. up1 = relu(bn1(lc1 @ Bt)) -> out[0:256*NPIX] + up1T -> g_v  (HMMA dual)
    mma_gemm<4><<<dim3(128, 2), 256, GEMM_SMEM>>>(Ah + 1179648, Al + 1179648, Bh, Bl,
                                                  out, vv, 2304, bns, bnb);
    // 13. im2col(up1T) -> Bt
    im2colT<<<NPIX, 256>>>(vv);
    // 14. up2 = relu(bn2(lc2 @ Bt)) -> out[256*NPIX:]  (HMMA)
    mma_gemm<3><<<dim3(128, 2), 256, GEMM_SMEM>>>(Ah + 1769472, Al + 1769472, Bh, Bl,
                                                  out + (size_t)256 * NPIX, nullptr, 2304,
                                                  bns + 256, bnb + 256);
}

// round 5
// speedup vs baseline: 2.3385x; 1.1614x over previous
#include <cuda_runtime.h>
#include <cuda_bf16.h>
#include <math.h>
#include <stdint.h>

#define NPIX 16384          // 128*128
#define QPAD 17024          // 16900 padded-pixel count rounded to 128-tile multiple

// ---------------- static device scratch (no allocations allowed) ----------------
__device__ __align__(16) float  g_cc  [512 * NPIX];          // [xu(256) ; Cf(256)] chan-major
__device__ __align__(16) float  g_ccpT[QPAD * 512];          // padded map, [q][c] chan-fastest
__device__ __align__(16) float  g_v   [256 * NPIX];          // v; then CfT; then up1T
__device__ __align__(16) float  g_u   [256 * NPIX];          // u; then famT
__device__ __align__(16) float  g_off [ 18 * NPIX];
__device__ __align__(16) int4   g_idx [9 * NPIX];
__device__ __align__(16) float4 g_wt  [9 * NPIX];
__device__ __align__(16) float  g_bnscale[512];
__device__ __align__(16) float  g_bnbias [512];
// bf16 hi/lo of padded map for the 9 deform GEMMs
__device__ __align__(16) __nv_bfloat16 g_cbh[QPAD * 512];
__device__ __align__(16) __nv_bfloat16 g_cbl[QPAD * 512];
// workspace: Y[9][QPAD][256] fp32 (157MB), later Bh/Bl bf16 [NPIX][2304] (75.5MB each)
#define Y_BYTES   ((size_t)9 * QPAD * 256 * 4)
__device__ __align__(16) char g_ws[Y_BYTES];
#define BHL_OFF   ((size_t)NPIX * 2304 * 2)
// bf16 hi/lo weight planes (k-permuted): dc @0, lc1 @1179648, lc2 @1769472
__device__ __align__(16) __nv_bfloat16 g_Ah[2359296];
__device__ __align__(16) __nv_bfloat16 g_Al[2359296];

// ---------------- PTX helpers (baseline compute_103 ISA only) ----------------
__device__ __forceinline__ uint32_t smem_u32(const void* p) {
    uint32_t a;
    asm("{ .reg .u64 t; cvta.to.shared.u64 t, %1; cvt.u32.u64 %0, t; }" : "=r"(a) : "l"(p));
    return a;
}
#define CP_ASYNC16(dst, src) \
    asm volatile("cp.async.cg.shared.global [%0], [%1], 16;" :: "r"(dst), "l"(src))
#define CP_COMMIT() asm volatile("cp.async.commit_group;")
#define CP_WAIT1()  asm volatile("cp.async.wait_group 1;" ::: "memory")
#define CP_WAIT0()  asm volatile("cp.async.wait_group 0;" ::: "memory")

__device__ __forceinline__ void ldsm4(uint32_t r[4], uint32_t addr) {
    asm volatile("ldmatrix.sync.aligned.m8n8.x4.shared.b16 {%0,%1,%2,%3}, [%4];"
                 : "=r"(r[0]), "=r"(r[1]), "=r"(r[2]), "=r"(r[3]) : "r"(addr));
}
__device__ __forceinline__ void mma_bf16(float c[4], const uint32_t a[4],
                                         uint32_t b0, uint32_t b1) {
    asm volatile("mma.sync.aligned.m16n8k16.row.col.f32.bf16.bf16.f32 "
                 "{%0,%1,%2,%3}, {%4,%5,%6,%7}, {%8,%9}, {%0,%1,%2,%3};"
                 : "+f"(c[0]), "+f"(c[1]), "+f"(c[2]), "+f"(c[3])
                 : "r"(a[0]), "r"(a[1]), "r"(a[2]), "r"(a[3]), "r"(b0), "r"(b1));
}

// ---------------- BN coefficient precompute ----------------
__global__ void bncoef_k(const float* __restrict__ g1, const float* __restrict__ b1,
                         const float* __restrict__ m1, const float* __restrict__ v1,
                         const float* __restrict__ g2, const float* __restrict__ b2,
                         const float* __restrict__ m2, const float* __restrict__ v2)
{
    int i = threadIdx.x;
    if (i < 256) {
        float s = g1[i] / sqrtf(v1[i] + 1e-5f);
        g_bnscale[i] = s;
        g_bnbias[i]  = b1[i] - m1[i] * s;
    } else {
        int j = i - 256;
        float s = g2[j] / sqrtf(v2[j] + 1e-5f);
        g_bnscale[i] = s;
        g_bnbias[i]  = b2[j] - m2[j] * s;
    }
}

// ---------------- weight hi/lo split with K permutation: k = kp*C + c ----------------
__global__ void split_perm(const float* __restrict__ w, __nv_bfloat16* __restrict__ hi,
                           __nv_bfloat16* __restrict__ lo, int C, int n)
{
    int t = blockIdx.x * 256 + threadIdx.x;
    if (t >= n) return;
    int K = C * 9;
    int o = t / K, r = t - o * K;
    int c = r / 9, kp = r - c * 9;
    int dst = o * K + kp * C + c;
    float v = w[t];
    __nv_bfloat16 h = __float2bfloat16(v);
    hi[dst] = h;
    lo[dst] = __float2bfloat16(v - __bfloat162float(h));
}

// ---------------- bilinear upsample 32x32 -> 128x128, align_corners=True ----------------
__global__ void upsample_k(const float* __restrict__ x)
{
    int t = blockIdx.x * 256 + threadIdx.x;
    int pix = t & (NPIX - 1);
    int c   = t >> 14;
    int oy = pix >> 7, ox = pix & 127;
    const float s = 31.0f / 127.0f;
    float fy = oy * s, fx = ox * s;
    int y0 = (int)floorf(fy); int y1 = min(y0 + 1, 31);
    int x0 = (int)floorf(fx); int x1 = min(x0 + 1, 31);
    float wy = fy - (float)y0;
    float wx = fx - (float)x0;
    const float* xc = x + c * 1024;
    float v00 = xc[y0 * 32 + x0], v01 = xc[y0 * 32 + x1];
    float v10 = xc[y1 * 32 + x0], v11 = xc[y1 * 32 + x1];
    float r0 = v00 * (1.0f - wy) + v10 * wy;
    float r1 = v01 * (1.0f - wy) + v11 * wy;
    g_cc[t] = r0 * (1.0f - wx) + r1 * wx;
}

// ---------------- FFMA SGEMM for the two small K=256 GEMMs ----------------
// EPI: 0 none, 1 sigmoid, 6 none + transposed copy Ct[n][256]
template<int EPI>
__global__ void __launch_bounds__(256, 2) sgemm_epi(
    const float* __restrict__ A, const float* __restrict__ B, float* __restrict__ C,
    float* __restrict__ Ct, int K)
{
    __shared__ float As[16][128];
    __shared__ float Bs[16][128];
    const int tid  = threadIdx.x;
    const int brow = blockIdx.y * 128;
    const int bcol = blockIdx.x * 128;
    const int ty = tid >> 4, tx = tid & 15;

    float acc[8][8];
#pragma unroll
    for (int i = 0; i < 8; i++)
#pragma unroll
        for (int j = 0; j < 8; j++) acc[i][j] = 0.0f;

    for (int k0 = 0; k0 < K; k0 += 16) {
#pragma unroll
        for (int l = 0; l < 2; l++) {
            int f = tid + l * 256;
            int ar = f >> 2, akq = f & 3;
            float4 av = *(const float4*)(A + (size_t)(brow + ar) * K + k0 + akq * 4);
            As[akq * 4 + 0][ar] = av.x;
            As[akq * 4 + 1][ar] = av.y;
            As[akq * 4 + 2][ar] = av.z;
            As[akq * 4 + 3][ar] = av.w;
            int bkr = f >> 5, bcq = f & 31;
            *(float4*)(&Bs[bkr][bcq * 4]) =
                *(const float4*)(B + (size_t)(k0 + bkr) * NPIX + bcol + bcq * 4);
        }
        __syncthreads();
#pragma unroll
        for (int kk = 0; kk < 16; kk++) {
            float ra[8], rb[8];
#pragma unroll
            for (int i = 0; i < 8; i++) ra[i] = As[kk][ty * 8 + i];
#pragma unroll
            for (int j = 0; j < 8; j++) rb[j] = Bs[kk][tx * 8 + j];
#pragma unroll
            for (int i = 0; i < 8; i++)
#pragma unroll
                for (int j = 0; j < 8; j++)
                    acc[i][j] = fmaf(ra[i], rb[j], acc[i][j]);
        }
        __syncthreads();
    }
#pragma unroll
    for (int i = 0; i < 8; i++) {
        int row = brow + ty * 8 + i;
#pragma unroll
        for (int j = 0; j < 8; j++) {
            int col = bcol + tx * 8 + j;
            float v = acc[i][j];
            if (EPI == 1) v = 1.0f / (1.0f + expf(-v));
            C[(size_t)row * NPIX + col] = v;
        }
    }
    if (EPI == 6) {
        // transposed copy: Ct[(col)][row], 8 consecutive rows per (thread, j)
#pragma unroll
        for (int j = 0; j < 8; j++) {
            int col = bcol + tx * 8 + j;
            float4 a = make_float4(acc[0][j], acc[1][j], acc[2][j], acc[3][j]);
            float4 b = make_float4(acc[4][j], acc[5][j], acc[6][j], acc[7][j]);
            *(float4*)(Ct + (size_t)col * 256 + brow + ty * 8)     = a;
            *(float4*)(Ct + (size_t)col * 256 + brow + ty * 8 + 4) = b;
        }
    }
}

// ---------------- per-channel 128x128x128 matmul: u[c] = llf[c] @ v[c] + llf[c] ----------------
__global__ void __launch_bounds__(256, 2) chan_matmul(const float* __restrict__ llf)
{
    const int c = blockIdx.x;
    const float* A = llf + (size_t)c * NPIX;
    const float* B = g_v + (size_t)c * NPIX;
    float*       C = g_u + (size_t)c * NPIX;

    __shared__ float As[16][128];
    __shared__ float Bs[16][128];
    const int tid = threadIdx.x;
    const int ty = tid >> 4, tx = tid & 15;

    float acc[8][8];
#pragma unroll
    for (int i = 0; i < 8; i++)
#pragma unroll
        for (int j = 0; j < 8; j++) acc[i][j] = 0.0f;

    for (int k0 = 0; k0 < 128; k0 += 16) {
#pragma unroll
        for (int l = 0; l < 2; l++) {
            int f = tid + l * 256;
            int ar = f >> 2, akq = f & 3;
            float4 av = *(const float4*)(A + ar * 128 + k0 + akq * 4);
            As[akq * 4 + 0][ar] = av.x;
            As[akq * 4 + 1][ar] = av.y;
            As[akq * 4 + 2][ar] = av.z;
            As[akq * 4 + 3][ar] = av.w;
            int bkr = f >> 5, bcq = f & 31;
            *(float4*)(&Bs[bkr][bcq * 4]) = *(const float4*)(B + (k0 + bkr) * 128 + bcq * 4);
        }
        __syncthreads();
#pragma unroll
        for (int kk = 0; kk < 16; kk++) {
            float ra[8], rb[8];
#pragma unroll
            for (int i = 0; i < 8; i++) ra[i] = As[kk][ty * 8 + i];
#pragma unroll
            for (int j = 0; j < 8; j++) rb[j] = Bs[kk][tx * 8 + j];
#pragma unroll
            for (int i = 0; i < 8; i++)
#pragma unroll
                for (int j = 0; j < 8; j++)
                    acc[i][j] = fmaf(ra[i], rb[j], acc[i][j]);
        }
        __syncthreads();
    }
#pragma unroll
    for (int i = 0; i < 8; i++) {
        int row = ty * 8 + i;
#pragma unroll
        for (int j = 0; j < 8; j++) {
            int col = tx * 8 + j;
            C[row * 128 + col] = acc[i][j] + A[row * 128 + col];
        }
    }
}

// ---------------- offsets conv (implicit im2col): off = p_w(18x4608) @ im2col(cc) + p_b ----
__global__ void __launch_bounds__(512) gemm_off(const float* __restrict__ A,
                                                const float* __restrict__ bias)
{
    const int K = 4608, KG = 1152;
    __shared__ float Ash[4][16][18];
    __shared__ float red[4][18][128];
    int tid  = threadIdx.x;
    int g    = tid >> 7;
    int lane = tid & 127;
    int pix  = blockIdx.x * 128 + lane;
    int h = pix >> 7, w = pix & 127;

    float acc[18];
#pragma unroll
    for (int o = 0; o < 18; o++) acc[o] = 0.0f;

    for (int kc = 0; kc < KG; kc += 16) {
        int k0 = g * KG + kc;
        for (int i = lane; i < 288; i += 128) {
            int o = i / 16, kk = i % 16;
            Ash[g][kk][o] = A[o * K + k0 + kk];
        }
        __syncthreads();
#pragma unroll 4
        for (int kk = 0; kk < 16; kk++) {
            int k = k0 + kk;
            int c = k / 9, r = k - c * 9;
            int kh = r / 3, kw = r - kh * 3;
            int ih = h + kh - 1, iw = w + kw - 1;
            float b = 0.0f;
            if ((unsigned)ih < 128u && (unsigned)iw < 128u)
                b = g_cc[((size_t)c << 14) + (ih << 7) + iw];
#pragma unroll
            for (int o = 0; o < 18; o++) acc[o] = fmaf(Ash[g][kk][o], b, acc[o]);
        }
        __syncthreads();
    }
#pragma unroll
    for (int o = 0; o < 18; o++) red[g][o][lane] = acc[o];
    __syncthreads();
    if (g == 0) {
#pragma unroll
        for (int o = 0; o < 18; o++) {
            float s = red[0][o][lane] + red[1][o][lane] + red[2][o][lane] + red[3][o][lane]
                    + bias[o];
            g_off[o * NPIX + pix] = s;
        }
    }
}

// ---------------- zero border rows of ccpT ----------------
__global__ void border_zero_k()
{
    int t = blockIdx.x * 256 + threadIdx.x;       // 516 * 512
    if (t >= 516 * 512) return;
    int b = t >> 9, c = t & 511;
    int q;
    if (b < 130)       q = b;
    else if (b < 260)  q = 129 * 130 + (b - 130);
    else {
        int r = b - 260;
        int hh = 1 + (r >> 1);
        int ww = (r & 1) ? 129 : 0;
        q = hh * 130 + ww;
    }
    g_ccpT[(size_t)q * 512 + c] = 0.0f;
}

// ---------------- tiled transpose+pad: cc[c][pix] -> ccpT[(h+1)*130+w+1][c] ----------------
__global__ void transpose_pad_k()
{
    __shared__ float sm[32][33];
    int h  = blockIdx.x;
    int w0 = blockIdx.y * 32;
    int c0 = blockIdx.z * 32;
    int tx = threadIdx.x, ty = threadIdx.y;   // 32 x 8
#pragma unroll
    for (int i = 0; i < 4; i++)
        sm[ty + 8 * i][tx] = g_cc[(size_t)(c0 + ty + 8 * i) * NPIX + h * 128 + w0 + tx];
    __syncthreads();
#pragma unroll
    for (int i = 0; i < 4; i++)
        g_ccpT[(size_t)((h + 1) * 130 + (w0 + ty + 8 * i + 1)) * 512 + c0 + tx] =
            sm[tx][ty + 8 * i];
}

// ---------------- ccpT -> bf16 hi/lo planes ----------------
__global__ void cvt_cbhl()
{
    size_t t = (size_t)blockIdx.x * 256 + threadIdx.x;   // QPAD*512 threads
    float v = g_ccpT[t];
    __nv_bfloat16 h = __float2bfloat16(v);
    g_cbh[t] = h;
    g_cbl[t] = __float2bfloat16(v - __bfloat162float(h));
}

// ---------------- deform sampling coords + bilinear weights ----------------
__global__ void coords_k()
{
    int t = blockIdx.x * 256 + threadIdx.x;        // 9*NPIX, layout [k][pix]
    int pix = t & (NPIX - 1);
    int k   = t >> 14;
    int h = pix >> 7, w = pix & 127;
    float pnx = (float)(k / 3 - 1);
    float pny = (float)(k % 3 - 1);
    float px = g_off[k * NPIX + pix]       + pnx + (float)(h + 1);
    float py = g_off[(9 + k) * NPIX + pix] + pny + (float)(w + 1);
    float fx = floorf(px), fy = floorf(py);
    float x0 = fminf(fmaxf(fx,        0.0f), 129.0f);
    float x1 = fminf(fmaxf(fx + 1.0f, 0.0f), 129.0f);
    float y0 = fminf(fmaxf(fy,        0.0f), 129.0f);
    float y1 = fminf(fmaxf(fy + 1.0f, 0.0f), 129.0f);
    float pxc = fminf(fmaxf(px, 0.0f), 129.0f);
    float pyc = fminf(fmaxf(py, 0.0f), 129.0f);
    float glt = (1.0f + (x0 - pxc)) * (1.0f + (y0 - pyc));
    float grb = (1.0f - (x1 - pxc)) * (1.0f - (y1 - pyc));
    float glb = (1.0f + (x0 - pxc)) * (1.0f - (y1 - pyc));
    float grt = (1.0f - (x1 - pxc)) * (1.0f + (y0 - pyc));
    int ix0 = (int)x0, ix1 = (int)x1, iy0 = (int)y0, iy1 = (int)y1;
    g_idx[t] = make_int4(ix0 * 130 + iy0, ix1 * 130 + iy1, ix0 * 130 + iy1, ix1 * 130 + iy0);
    g_wt[t]  = make_float4(glt, grb, glb, grt);
}

// ---------------- gather-sum: famT[pix][o] = CfT[pix][o] + sum_kp sum_corner g*Y[kp][q][o] ----
__global__ void __launch_bounds__(256) gathersum(const float* __restrict__ Y,
                                                 const float* __restrict__ CfT)
{
    __shared__ int4   sid[9];
    __shared__ float4 swt[9];
    int pix = blockIdx.x;
    int t   = threadIdx.x;
    if (t < 9) {
        sid[t] = g_idx[t * NPIX + pix];
        swt[t] = g_wt [t * NPIX + pix];
    }
    __syncthreads();
    float acc = CfT[(size_t)pix * 256 + t];
#pragma unroll
    for (int kp = 0; kp < 9; kp++) {
        const float* Yk = Y + (size_t)kp * QPAD * 256;
        int4   id = sid[kp];
        float4 w  = swt[kp];
        acc += w.x * Yk[(size_t)id.x * 256 + t] + w.y * Yk[(size_t)id.y * 256 + t]
             + w.z * Yk[(size_t)id.z * 256 + t] + w.w * Yk[(size_t)id.w * 256 + t];
    }
    g_u[(size_t)pix * 256 + t] = acc;      // famT
}

// ---------------- coalesced im2col from transposed activation T[pix][256] ----------------
__global__ void __launch_bounds__(256) im2colT(const float* __restrict__ T)
{
    __nv_bfloat16* Bh = (__nv_bfloat16*)g_ws;
    __nv_bfloat16* Bl = (__nv_bfloat16*)(g_ws + BHL_OFF);
    int pix = blockIdx.x;
    int c   = threadIdx.x;
    int h = pix >> 7, w = pix & 127;
    size_t ob = (size_t)pix * 2304;
#pragma unroll
    for (int kp = 0; kp < 9; kp++) {
        int kh = kp / 3, kw = kp - kh * 3;
        int ih = h + kh - 1, iw = w + kw - 1;
        float v = 0.0f;
        if ((unsigned)ih < 128u && (unsigned)iw < 128u)
            v = T[(size_t)(ih * 128 + iw) * 256 + c];
        __nv_bfloat16 hh = __float2bfloat16(v);
        Bh[ob + kp * 256 + c] = hh;
        Bl[ob + kp * 256 + c] = __float2bfloat16(v - __bfloat162float(hh));
    }
}

// ---------------- HMMA bf16 split GEMM (2-stage, occupancy 2) ----------------
// D[m][n] = sum_k (Ah+Al)[m][k]*(Bh+Bl)[n][k] via 3 terms, fp32 accum.
// Tile 128x128, BK=32, 8 warps (2x4), warp tile 64x32.
// EPI 3: relu(x*e1[row]+e2[row]) -> C[m][NPIX]
// EPI 4: EPI3 + transposed store Ct[n][256]
// EPI 5: raw -> transposed store only into Y (n index offset by blockIdx.z*QPAD)
#define BK        32
#define ASTRIDE   40
#define PLANE_B   (128 * ASTRIDE * 2)      // 10240 B
#define STAGE_B   (4 * PLANE_B)            // 40960 B
#define GEMM_SMEM (2 * STAGE_B)            // 81920 B

__device__ __forceinline__ void issue_stage(
    uint32_t sb, int stage, const __nv_bfloat16* __restrict__ pA_h,
    const __nv_bfloat16* __restrict__ pA_l, const __nv_bfloat16* __restrict__ pB_h,
    const __nv_bfloat16* __restrict__ pB_l, int sA, int sB, int k0, int tid)
{
    uint32_t stb = sb + stage * STAGE_B;
#pragma unroll
    for (int q = 0; q < 2; q++) {
        int id  = tid * 2 + q;
        int row = id >> 2, seg = id & 3;
        uint32_t doff = (row * ASTRIDE + seg * 8) * 2;
        size_t aoff = (size_t)row * sA + k0 + seg * 8;
        size_t boff = (size_t)row * sB + k0 + seg * 8;
        CP_ASYNC16(stb + doff,               pA_h + aoff);
        CP_ASYNC16(stb + PLANE_B + doff,     pA_l + aoff);
        CP_ASYNC16(stb + 2 * PLANE_B + doff, pB_h + boff);
        CP_ASYNC16(stb + 3 * PLANE_B + doff, pB_l + boff);
    }
    CP_COMMIT();
}

template<int EPI>
__global__ void __launch_bounds__(256, 2) mma_gemm(
    const __nv_bfloat16* __restrict__ Ah, const __nv_bfloat16* __restrict__ Al,
    const __nv_bfloat16* __restrict__ Bh, const __nv_bfloat16* __restrict__ Bl,
    float* __restrict__ C, float* __restrict__ Ct, int K, int sA, int sB,
    const float* __restrict__ e1, const float* __restrict__ e2)
{
    extern __shared__ char sm[];
    uint32_t sb = smem_u32(sm);
    const int tid = threadIdx.x;
    const int wid = tid >> 5, lane = tid & 31;
    const int wr = wid >> 2, wc = wid & 3;
    const int brow = blockIdx.y * 128, bcol = blockIdx.x * 128;
    const int zz = blockIdx.z;                       // kp for EPI 5, else 0

    const __nv_bfloat16* pA_h = Ah + (size_t)brow * sA + zz * 512;
    const __nv_bfloat16* pA_l = Al + (size_t)brow * sA + zz * 512;
    const __nv_bfloat16* pB_h = Bh + (size_t)bcol * sB;
    const __nv_bfloat16* pB_l = Bl + (size_t)bcol * sB;

    float acc[4][4][4];
#pragma unroll
    for (int i = 0; i < 4; i++)
#pragma unroll
        for (int j = 0; j < 4; j++)
#pragma unroll
            for (int q = 0; q < 4; q++) acc[i][j][q] = 0.0f;

    const int sub = lane >> 3, rr = lane & 7;
    const int am = wr * 64 + (sub & 1) * 8 + rr;
    const int ak = (sub >> 1) * 8;
    const int bn = wc * 32 + (sub >> 1) * 8 + rr;
    const int bk = (sub & 1) * 8;

    const int NC = K / BK;
    issue_stage(sb, 0, pA_h, pA_l, pB_h, pB_l, sA, sB, 0, tid);
    issue_stage(sb, 1, pA_h, pA_l, pB_h, pB_l, sA, sB, BK, tid);

    for (int ci = 0; ci < NC; ci++) {
        if (ci + 1 < NC) CP_WAIT1(); else CP_WAIT0();
        __syncthreads();

        uint32_t stb = sb + (ci & 1) * STAGE_B;
#pragma unroll
        for (int ks = 0; ks < 2; ks++) {
            uint32_t ah[4][4], al[4][4], bh[4][2], bl[4][2];
#pragma unroll
            for (int mt = 0; mt < 4; mt++) {
                uint32_t aoff = ((am + mt * 16) * ASTRIDE + ks * 16 + ak) * 2;
                ldsm4(ah[mt], stb + aoff);
                ldsm4(al[mt], stb + PLANE_B + aoff);
            }
#pragma unroll
            for (int ntp = 0; ntp < 2; ntp++) {
                uint32_t boff = ((bn + ntp * 16) * ASTRIDE + ks * 16 + bk) * 2;
                uint32_t rh[4], rl[4];
                ldsm4(rh, stb + 2 * PLANE_B + boff);
                ldsm4(rl, stb + 3 * PLANE_B + boff);
                bh[ntp * 2 + 0][0] = rh[0]; bh[ntp * 2 + 0][1] = rh[1];
                bh[ntp * 2 + 1][0] = rh[2]; bh[ntp * 2 + 1][1] = rh[3];
                bl[ntp * 2 + 0][0] = rl[0]; bl[ntp * 2 + 0][1] = rl[1];
                bl[ntp * 2 + 1][0] = rl[2]; bl[ntp * 2 + 1][1] = rl[3];
            }
#pragma unroll
            for (int mt = 0; mt < 4; mt++)
#pragma unroll
                for (int nt = 0; nt < 4; nt++) {
                    mma_bf16(acc[mt][nt], ah[mt], bh[nt][0], bh[nt][1]);
                    mma_bf16(acc[mt][nt], al[mt], bh[nt][0], bh[nt][1]);
                    mma_bf16(acc[mt][nt], ah[mt], bl[nt][0], bl[nt][1]);
                }
        }
        __syncthreads();
        if (ci + 2 < NC)
            issue_stage(sb, ci & 1, pA_h, pA_l, pB_h, pB_l, sA, sB, (ci + 2) * BK, tid);
    }

    // ---------------- epilogue ----------------
    const int gid = lane >> 2, t4 = lane & 3;
    float* smf = (float*)sm;                        // stride 132, 67.6KB <= 80KB
#pragma unroll
    for (int mt = 0; mt < 4; mt++) {
        int ml = wr * 64 + mt * 16 + gid;
        int m0 = brow + ml;
#pragma unroll
        for (int nt = 0; nt < 4; nt++) {
            int nl = wc * 32 + nt * 8 + t4 * 2;
            int n0 = bcol + nl;
            float v0, v1, v2, v3;
            if (EPI == 5) {
                v0 = acc[mt][nt][0]; v1 = acc[mt][nt][1];
                v2 = acc[mt][nt][2]; v3 = acc[mt][nt][3];
            } else {
                float s0 = e1[m0], b0 = e2[m0];
                float s1 = e1[m0 + 8], b1 = e2[m0 + 8];
                v0 = fmaxf(acc[mt][nt][0] * s0 + b0, 0.0f);
                v1 = fmaxf(acc[mt][nt][1] * s0 + b0, 0.0f);
                v2 = fmaxf(acc[mt][nt][2] * s1 + b1, 0.0f);
                v3 = fmaxf(acc[mt][nt][3] * s1 + b1, 0.0f);
                *(float2*)(C + (size_t)m0 * NPIX + n0)       = make_float2(v0, v1);
                *(float2*)(C + (size_t)(m0 + 8) * NPIX + n0) = make_float2(v2, v3);
            }
            if (EPI == 4 || EPI == 5) {
                smf[(nl)     * 132 + ml]     = v0;
                smf[(nl + 1) * 132 + ml]     = v1;
                smf[(nl)     * 132 + ml + 8] = v2;
                smf[(nl + 1) * 132 + ml + 8] = v3;
            }
        }
    }
    if (EPI == 4 || EPI == 5) {
        __syncthreads();
        size_t nbase = (size_t)zz * QPAD + bcol;
#pragma unroll 4
        for (int i = 0; i < 64; i++) {
            int idx = i * 256 + tid;
            int nl = idx >> 7, ml = idx & 127;
            Ct[(nbase + nl) * 256 + brow + ml] = smf[nl * 132 + ml];
        }
    }
}

// ---------------- host launcher ----------------
extern "C" void kernel_launch(void* const* d_in, const int* in_sizes, int n_in,
                              void* d_out, int out_size)
{
    (void)in_sizes; (void)n_in; (void)out_size;
    const float* x    = (const float*)d_in[0];
    const float* llf  = (const float*)d_in[1];
    const float* fm_w = (const float*)d_in[2];
    const float* fs_w = (const float*)d_in[3];
    const float* p_w  = (const float*)d_in[4];
    const float* p_b  = (const float*)d_in[5];
    const float* dc_w = (const float*)d_in[6];
    const float* lc1w = (const float*)d_in[7];
    const float* g1 = (const float*)d_in[8],  *b1 = (const float*)d_in[9];
    const float* m1 = (const float*)d_in[10], *v1 = (const float*)d_in[11];
    const float* lc2w = (const float*)d_in[12];
    const float* g2 = (const float*)d_in[13], *b2 = (const float*)d_in[14];
    const float* m2 = (const float*)d_in[15], *v2 = (const float*)d_in[16];
    float* out = (float*)d_out;

    float *cc, *vv, *uu, *bns, *bnb;
    __nv_bfloat16 *Ah, *Al, *cbh, *cbl;
    char* ws;
    cudaGetSymbolAddress((void**)&cc,  g_cc);
    cudaGetSymbolAddress((void**)&vv,  g_v);
    cudaGetSymbolAddress((void**)&uu,  g_u);
    cudaGetSymbolAddress((void**)&bns, g_bnscale);
    cudaGetSymbolAddress((void**)&bnb, g_bnbias);
    cudaGetSymbolAddress((void**)&Ah,  g_Ah);
    cudaGetSymbolAddress((void**)&Al,  g_Al);
    cudaGetSymbolAddress((void**)&cbh, g_cbh);
    cudaGetSymbolAddress((void**)&cbl, g_cbl);
    cudaGetSymbolAddress((void**)&ws,  g_ws);
    float* Y = (float*)ws;
    __nv_bfloat16* Bh = (__nv_bfloat16*)ws;
    __nv_bfloat16* Bl = (__nv_bfloat16*)(ws + BHL_OFF);

    cudaFuncSetAttribute(mma_gemm<3>, cudaFuncAttributeMaxDynamicSharedMemorySize, GEMM_SMEM);
    cudaFuncSetAttribute(mma_gemm<4>, cudaFuncAttributeMaxDynamicSharedMemorySize, GEMM_SMEM);
    cudaFuncSetAttribute(mma_gemm<5>, cudaFuncAttributeMaxDynamicSharedMemorySize, GEMM_SMEM);

    // 1. BN coefficients + permuted weight splits
    bncoef_k<<<1, 512>>>(g1, b1, m1, v1, g2, b2, m2, v2);
    split_perm<<<(1179648 + 255) / 256, 256>>>(dc_w, Ah, Al, 512, 1179648);
    split_perm<<<(589824 + 255) / 256, 256>>>(lc1w, Ah + 1179648, Al + 1179648, 256, 589824);
    split_perm<<<(589824 + 255) / 256, 256>>>(lc2w, Ah + 1769472, Al + 1769472, 256, 589824);
    // 2. xu -> cc[0:256]
    upsample_k<<<NPIX, 256>>>(x);
    // 3. v = sigmoid(fm_w @ llf)
    sgemm_epi<1><<<dim3(128, 2), 256>>>(fm_w, llf, vv, nullptr, 256);
    // 4. u[c] = llf[c] @ v[c] + llf[c]
    chan_matmul<<<256, 256>>>(llf);
    // 5. Cf = fs_w @ u -> cc[256:512] (+ CfT -> g_v)
    sgemm_epi<6><<<dim3(128, 2), 256>>>(fs_w, uu, cc + (size_t)256 * NPIX, vv, 256);
    // 6. offsets = p_w @ im2col(cc) + p_b
    gemm_off<<<NPIX / 128, 512>>>(p_w, p_b);
    // 7. ccpT = pad+transpose(cc); bf16 hi/lo planes
    border_zero_k<<<(516 * 512 + 255) / 256, 256>>>();
    transpose_pad_k<<<dim3(128, 4, 16), dim3(32, 8)>>>();
    cvt_cbhl<<<QPAD * 2, 256>>>();
    // 8. bilinear coords/weights
    coords_k<<<9 * NPIX / 256, 256>>>();
    // 9. Y[kp] = (dc_w_kp @ ccpT^T)^T, 9 GEMMs in one launch
    mma_gemm<5><<<dim3(QPAD / 128, 2, 9), 256, GEMM_SMEM>>>(
        Ah, Al, cbh, cbl, nullptr, Y, 512, 4608, 512, nullptr, nullptr);
    // 10. famT = gathersum(Y) + CfT -> g_u
    gathersum<<<NPIX, 256>>>(Y, vv);
    // 11. im2col(famT) -> Bh/Bl
    im2colT<<<NPIX, 256>>>(uu);
    // 12. up1 = relu(bn1(lc1 @ Bt)) -> out[0:256*NPIX] + up1T -> g_v
    mma_gemm<4><<<dim3(128, 2), 256, GEMM_SMEM>>>(
        Ah + 1179648, Al + 1179648, Bh, Bl, out, vv, 2304, 2304, 2304, bns, bnb);
    // 13. im2col(up1T) -> Bh/Bl
    im2colT<<<NPIX, 256>>>(vv);
    // 14. up2 = relu(bn2(lc2 @ Bt)) -> out[256*NPIX:]
    mma_gemm<3><<<dim3(128, 2), 256, GEMM_SMEM>>>(
        Ah + 1769472, Al + 1769472, Bh, Bl, out + (size_t)256 * NPIX, nullptr,
        2304, 2304, 2304, bns + 256, bnb + 256);
}

// round 6
// speedup vs baseline: 2.6461x; 1.1315x over previous
#include <cuda_runtime.h>
#include <cuda_bf16.h>
#include <math.h>
#include <stdint.h>

#define NPIX 16384          // 128*128
#define QPAD 17024          // 16900 padded positions rounded up to 128 multiple

// ---------------- static device scratch (no allocations allowed) ----------------
__device__ __align__(16) float  g_cc  [512 * NPIX];          // [xu(256) ; Cf(256)] chan-major
__device__ __align__(16) float  g_v   [256 * NPIX];          // v; then CfT
__device__ __align__(16) float  g_u   [256 * NPIX];          // u; then Z[9][1024][256]
__device__ __align__(16) float  g_off [ 18 * NPIX];
__device__ __align__(16) int4   g_idx [9 * NPIX];
__device__ __align__(16) float4 g_wt  [9 * NPIX];
__device__ __align__(16) float  g_bnscale[512];
__device__ __align__(16) float  g_bnbias [512];
// bf16 hi/lo of padded Cf map [q][256]
__device__ __align__(16) __nv_bfloat16 g_cbh[QPAD * 256];
__device__ __align__(16) __nv_bfloat16 g_cbl[QPAD * 256];
// bf16 hi/lo of x32 transposed [s=1024][256]
__device__ __align__(16) __nv_bfloat16 g_xbh[1024 * 256];
__device__ __align__(16) __nv_bfloat16 g_xbl[1024 * 256];
// workspace: Y[9][QPAD][256] fp32, then famT / up1T bf16 hi/lo planes
#define Y_BYTES   ((size_t)9 * QPAD * 256 * 4)
#define PLANE_SZ  ((size_t)NPIX * 256 * 2)
#define FH_OFF    (Y_BYTES)
#define FL_OFF    (Y_BYTES + PLANE_SZ)
#define U1H_OFF   (Y_BYTES + 2 * PLANE_SZ)
#define U1L_OFF   (Y_BYTES + 3 * PLANE_SZ)
__device__ __align__(16) char g_ws[Y_BYTES + 4 * PLANE_SZ];
// bf16 hi/lo weight planes (k-permuted): dc @0, lc1 @1179648, lc2 @1769472
__device__ __align__(16) __nv_bfloat16 g_Ah[2359296];
__device__ __align__(16) __nv_bfloat16 g_Al[2359296];

// ---------------- PTX helpers (baseline compute_103 ISA only) ----------------
__device__ __forceinline__ uint32_t smem_u32(const void* p) {
    uint32_t a;
    asm("{ .reg .u64 t; cvta.to.shared.u64 t, %1; cvt.u32.u64 %0, t; }" : "=r"(a) : "l"(p));
    return a;
}
#define CP_ASYNC16(dst, src) \
    asm volatile("cp.async.cg.shared.global [%0], [%1], 16;" :: "r"(dst), "l"(src))
#define CP_ASYNC16Z(dst, src, sz) \
    asm volatile("cp.async.cg.shared.global [%0], [%1], 16, %2;" :: "r"(dst), "l"(src), "r"(sz))
#define CP_COMMIT() asm volatile("cp.async.commit_group;")
#define CP_WAIT1()  asm volatile("cp.async.wait_group 1;" ::: "memory")
#define CP_WAIT0()  asm volatile("cp.async.wait_group 0;" ::: "memory")

__device__ __forceinline__ void ldsm4(uint32_t r[4], uint32_t addr) {
    asm volatile("ldmatrix.sync.aligned.m8n8.x4.shared.b16 {%0,%1,%2,%3}, [%4];"
                 : "=r"(r[0]), "=r"(r[1]), "=r"(r[2]), "=r"(r[3]) : "r"(addr));
}
__device__ __forceinline__ void mma_bf16(float c[4], const uint32_t a[4],
                                         uint32_t b0, uint32_t b1) {
    asm volatile("mma.sync.aligned.m16n8k16.row.col.f32.bf16.bf16.f32 "
                 "{%0,%1,%2,%3}, {%4,%5,%6,%7}, {%8,%9}, {%0,%1,%2,%3};"
                 : "+f"(c[0]), "+f"(c[1]), "+f"(c[2]), "+f"(c[3])
                 : "r"(a[0]), "r"(a[1]), "r"(a[2]), "r"(a[3]), "r"(b0), "r"(b1));
}

// ---------------- BN coefficient precompute ----------------
__global__ void bncoef_k(const float* __restrict__ g1, const float* __restrict__ b1,
                         const float* __restrict__ m1, const float* __restrict__ v1,
                         const float* __restrict__ g2, const float* __restrict__ b2,
                         const float* __restrict__ m2, const float* __restrict__ v2)
{
    int i = threadIdx.x;
    if (i < 256) {
        float s = g1[i] / sqrtf(v1[i] + 1e-5f);
        g_bnscale[i] = s;
        g_bnbias[i]  = b1[i] - m1[i] * s;
    } else {
        int j = i - 256;
        float s = g2[j] / sqrtf(v2[j] + 1e-5f);
        g_bnscale[i] = s;
        g_bnbias[i]  = b2[j] - m2[j] * s;
    }
}

// ---------------- weight hi/lo split with K permutation: k = kp*C + c ----------------
__global__ void split_perm(const float* __restrict__ w, __nv_bfloat16* __restrict__ hi,
                           __nv_bfloat16* __restrict__ lo, int C, int n)
{
    int t = blockIdx.x * 256 + threadIdx.x;
    if (t >= n) return;
    int K = C * 9;
    int o = t / K, r = t - o * K;
    int c = r / 9, kp = r - c * 9;
    int dst = o * K + kp * C + c;
    float v = w[t];
    __nv_bfloat16 h = __float2bfloat16(v);
    hi[dst] = h;
    lo[dst] = __float2bfloat16(v - __bfloat162float(h));
}

// ---------------- bilinear upsample 32x32 -> 128x128, align_corners=True ----------------
__global__ void upsample_k(const float* __restrict__ x)
{
    int t = blockIdx.x * 256 + threadIdx.x;
    int pix = t & (NPIX - 1);
    int c   = t >> 14;
    int oy = pix >> 7, ox = pix & 127;
    const float s = 31.0f / 127.0f;
    float fy = oy * s, fx = ox * s;
    int y0 = (int)floorf(fy); int y1 = min(y0 + 1, 31);
    int x0 = (int)floorf(fx); int x1 = min(x0 + 1, 31);
    float wy = fy - (float)y0;
    float wx = fx - (float)x0;
    const float* xc = x + c * 1024;
    float v00 = xc[y0 * 32 + x0], v01 = xc[y0 * 32 + x1];
    float v10 = xc[y1 * 32 + x0], v11 = xc[y1 * 32 + x1];
    float r0 = v00 * (1.0f - wy) + v10 * wy;
    float r1 = v01 * (1.0f - wy) + v11 * wy;
    g_cc[t] = r0 * (1.0f - wx) + r1 * wx;
}

// ---------------- transpose x: x[c][s] -> xbh/xbl [s][256] hi/lo ----------------
__global__ void transpose_x_bf(const float* __restrict__ x)
{
    __shared__ float sm[32][33];
    int s0 = blockIdx.x * 32, c0 = blockIdx.y * 32;
    int tx = threadIdx.x, ty = threadIdx.y;     // 32 x 8
#pragma unroll
    for (int i = 0; i < 4; i++)
        sm[ty + 8 * i][tx] = x[(c0 + ty + 8 * i) * 1024 + s0 + tx];
    __syncthreads();
#pragma unroll
    for (int i = 0; i < 4; i++) {
        float v = sm[tx][ty + 8 * i];
        int s = s0 + ty + 8 * i, c = c0 + tx;
        __nv_bfloat16 h = __float2bfloat16(v);
        g_xbh[s * 256 + c] = h;
        g_xbl[s * 256 + c] = __float2bfloat16(v - __bfloat162float(h));
    }
}

// ---------------- FFMA SGEMM for the two small K=256 GEMMs ----------------
// EPI: 1 sigmoid, 6 none + transposed copy Ct[n][256]
template<int EPI>
__global__ void __launch_bounds__(256, 2) sgemm_epi(
    const float* __restrict__ A, const float* __restrict__ B, float* __restrict__ C,
    float* __restrict__ Ct, int K)
{
    __shared__ float As[16][128];
    __shared__ float Bs[16][128];
    const int tid  = threadIdx.x;
    const int brow = blockIdx.y * 128;
    const int bcol = blockIdx.x * 128;
    const int ty = tid >> 4, tx = tid & 15;

    float acc[8][8];
#pragma unroll
    for (int i = 0; i < 8; i++)
#pragma unroll
        for (int j = 0; j < 8; j++) acc[i][j] = 0.0f;

    for (int k0 = 0; k0 < K; k0 += 16) {
#pragma unroll
        for (int l = 0; l < 2; l++) {
            int f = tid + l * 256;
            int ar = f >> 2, akq = f & 3;
            float4 av = *(const float4*)(A + (size_t)(brow + ar) * K + k0 + akq * 4);
            As[akq * 4 + 0][ar] = av.x;
            As[akq * 4 + 1][ar] = av.y;
            As[akq * 4 + 2][ar] = av.z;
            As[akq * 4 + 3][ar] = av.w;
            int bkr = f >> 5, bcq = f & 31;
            *(float4*)(&Bs[bkr][bcq * 4]) =
                *(const float4*)(B + (size_t)(k0 + bkr) * NPIX + bcol + bcq * 4);
        }
        __syncthreads();
#pragma unroll
        for (int kk = 0; kk < 16; kk++) {
            float ra[8], rb[8];
#pragma unroll
            for (int i = 0; i < 8; i++) ra[i] = As[kk][ty * 8 + i];
#pragma unroll
            for (int j = 0; j < 8; j++) rb[j] = Bs[kk][tx * 8 + j];
#pragma unroll
            for (int i = 0; i < 8; i++)
#pragma unroll
                for (int j = 0; j < 8; j++)
                    acc[i][j] = fmaf(ra[i], rb[j], acc[i][j]);
        }
        __syncthreads();
    }
#pragma unroll
    for (int i = 0; i < 8; i++) {
        int row = brow + ty * 8 + i;
#pragma unroll
        for (int j = 0; j < 8; j++) {
            int col = bcol + tx * 8 + j;
            float v = acc[i][j];
            if (EPI == 1) v = 1.0f / (1.0f + expf(-v));
            C[(size_t)row * NPIX + col] = v;
        }
    }
    if (EPI == 6) {
#pragma unroll
        for (int j = 0; j < 8; j++) {
            int col = bcol + tx * 8 + j;
            float4 a = make_float4(acc[0][j], acc[1][j], acc[2][j], acc[3][j]);
            float4 b = make_float4(acc[4][j], acc[5][j], acc[6][j], acc[7][j]);
            *(float4*)(Ct + (size_t)col * 256 + brow + ty * 8)     = a;
            *(float4*)(Ct + (size_t)col * 256 + brow + ty * 8 + 4) = b;
        }
    }
}

// ---------------- per-channel 128x128x128 matmul: u[c] = llf[c] @ v[c] + llf[c] ----------------
__global__ void __launch_bounds__(256, 2) chan_matmul(const float* __restrict__ llf)
{
    const int c = blockIdx.x;
    const float* A = llf + (size_t)c * NPIX;
    const float* B = g_v + (size_t)c * NPIX;
    float*       C = g_u + (size_t)c * NPIX;

    __shared__ float As[16][128];
    __shared__ float Bs[16][128];
    const int tid = threadIdx.x;
    const int ty = tid >> 4, tx = tid & 15;

    float acc[8][8];
#pragma unroll
    for (int i = 0; i < 8; i++)
#pragma unroll
        for (int j = 0; j < 8; j++) acc[i][j] = 0.0f;

    for (int k0 = 0; k0 < 128; k0 += 16) {
#pragma unroll
        for (int l = 0; l < 2; l++) {
            int f = tid + l * 256;
            int ar = f >> 2, akq = f & 3;
            float4 av = *(const float4*)(A + ar * 128 + k0 + akq * 4);
            As[akq * 4 + 0][ar] = av.x;
            As[akq * 4 + 1][ar] = av.y;
            As[akq * 4 + 2][ar] = av.z;
            As[akq * 4 + 3][ar] = av.w;
            int bkr = f >> 5, bcq = f & 31;
            *(float4*)(&Bs[bkr][bcq * 4]) = *(const float4*)(B + (k0 + bkr) * 128 + bcq * 4);
        }
        __syncthreads();
#pragma unroll
        for (int kk = 0; kk < 16; kk++) {
            float ra[8], rb[8];
#pragma unroll
            for (int i = 0; i < 8; i++) ra[i] = As[kk][ty * 8 + i];
#pragma unroll
            for (int j = 0; j < 8; j++) rb[j] = Bs[kk][tx * 8 + j];
#pragma unroll
            for (int i = 0; i < 8; i++)
#pragma unroll
                for (int j = 0; j < 8; j++)
                    acc[i][j] = fmaf(ra[i], rb[j], acc[i][j]);
        }
        __syncthreads();
    }
#pragma unroll
    for (int i = 0; i < 8; i++) {
        int row = ty * 8 + i;
#pragma unroll
        for (int j = 0; j < 8; j++) {
            int col = tx * 8 + j;
            C[row * 128 + col] = acc[i][j] + A[row * 128 + col];
        }
    }
}

// ---------------- offsets conv (implicit im2col): off = p_w(18x4608) @ im2col(cc) + p_b ----
__global__ void __launch_bounds__(512) gemm_off(const float* __restrict__ A,
                                                const float* __restrict__ bias)
{
    const int K = 4608, KG = 1152;
    __shared__ float Ash[4][16][18];
    __shared__ float red[4][18][128];
    int tid  = threadIdx.x;
    int g    = tid >> 7;
    int lane = tid & 127;
    int pix  = blockIdx.x * 128 + lane;
    int h = pix >> 7, w = pix & 127;

    float acc[18];
#pragma unroll
    for (int o = 0; o < 18; o++) acc[o] = 0.0f;

    for (int kc = 0; kc < KG; kc += 16) {
        int k0 = g * KG + kc;
        for (int i = lane; i < 288; i += 128) {
            int o = i / 16, kk = i % 16;
            Ash[g][kk][o] = A[o * K + k0 + kk];
        }
        __syncthreads();
#pragma unroll 4
        for (int kk = 0; kk < 16; kk++) {
            int k = k0 + kk;
            int c = k / 9, r = k - c * 9;
            int kh = r / 3, kw = r - kh * 3;
            int ih = h + kh - 1, iw = w + kw - 1;
            float b = 0.0f;
            if ((unsigned)ih < 128u && (unsigned)iw < 128u)
                b = g_cc[((size_t)c << 14) + (ih << 7) + iw];
#pragma unroll
            for (int o = 0; o < 18; o++) acc[o] = fmaf(Ash[g][kk][o], b, acc[o]);
        }
        __syncthreads();
    }
#pragma unroll
    for (int o = 0; o < 18; o++) red[g][o][lane] = acc[o];
    __syncthreads();
    if (g == 0) {
#pragma unroll
        for (int o = 0; o < 18; o++) {
            float s = red[0][o][lane] + red[1][o][lane] + red[2][o][lane] + red[3][o][lane]
                    + bias[o];
            g_off[o * NPIX + pix] = s;
        }
    }
}

// ---------------- zero border rows of cbh/cbl ----------------
__global__ void border_zero_cf()
{
    int t = blockIdx.x * 256 + threadIdx.x;       // 516 * 256
    if (t >= 516 * 256) return;
    int b = t >> 8, c = t & 255;
    int q;
    if (b < 130)       q = b;
    else if (b < 260)  q = 129 * 130 + (b - 130);
    else {
        int r = b - 260;
        int hh = 1 + (r >> 1);
        int ww = (r & 1) ? 129 : 0;
        q = hh * 130 + ww;
    }
    g_cbh[(size_t)q * 256 + c] = __float2bfloat16(0.0f);
    g_cbl[(size_t)q * 256 + c] = __float2bfloat16(0.0f);
}

// ---------------- transpose+pad Cf: cc[256+c][pix] -> cbh/cbl[(h+1)*130+w+1][c] ----------
__global__ void transpose_pad_cf()
{
    __shared__ float sm[32][33];
    int h  = blockIdx.x;
    int w0 = blockIdx.y * 32;
    int c0 = blockIdx.z * 32;
    int tx = threadIdx.x, ty = threadIdx.y;   // 32 x 8
#pragma unroll
    for (int i = 0; i < 4; i++)
        sm[ty + 8 * i][tx] =
            g_cc[(size_t)(256 + c0 + ty + 8 * i) * NPIX + h * 128 + w0 + tx];
    __syncthreads();
#pragma unroll
    for (int i = 0; i < 4; i++) {
        float v = sm[tx][ty + 8 * i];
        size_t q = (size_t)((h + 1) * 130 + (w0 + ty + 8 * i + 1)) * 256 + c0 + tx;
        __nv_bfloat16 hh = __float2bfloat16(v);
        g_cbh[q] = hh;
        g_cbl[q] = __float2bfloat16(v - __bfloat162float(hh));
    }
}

// ---------------- deform sampling coords + bilinear weights ----------------
__global__ void coords_k()
{
    int t = blockIdx.x * 256 + threadIdx.x;        // 9*NPIX, layout [k][pix]
    int pix = t & (NPIX - 1);
    int k   = t >> 14;
    int h = pix >> 7, w = pix & 127;
    float pnx = (float)(k / 3 - 1);
    float pny = (float)(k % 3 - 1);
    float px = g_off[k * NPIX + pix]       + pnx + (float)(h + 1);
    float py = g_off[(9 + k) * NPIX + pix] + pny + (float)(w + 1);
    float fx = floorf(px), fy = floorf(py);
    float x0 = fminf(fmaxf(fx,        0.0f), 129.0f);
    float x1 = fminf(fmaxf(fx + 1.0f, 0.0f), 129.0f);
    float y0 = fminf(fmaxf(fy,        0.0f), 129.0f);
    float y1 = fminf(fmaxf(fy + 1.0f, 0.0f), 129.0f);
    float pxc = fminf(fmaxf(px, 0.0f), 129.0f);
    float pyc = fminf(fmaxf(py, 0.0f), 129.0f);
    float glt = (1.0f + (x0 - pxc)) * (1.0f + (y0 - pyc));
    float grb = (1.0f - (x1 - pxc)) * (1.0f - (y1 - pyc));
    float glb = (1.0f + (x0 - pxc)) * (1.0f - (y1 - pyc));
    float grt = (1.0f - (x1 - pxc)) * (1.0f + (y0 - pyc));
    int ix0 = (int)x0, ix1 = (int)x1, iy0 = (int)y0, iy1 = (int)y1;
    g_idx[t] = make_int4(ix0 * 130 + iy0, ix1 * 130 + iy1, ix0 * 130 + iy1, ix1 * 130 + iy0);
    g_wt[t]  = make_float4(glt, grb, glb, grt);
}

// ---------------- gather-sum -> famT bf16 hi/lo planes ----------------
__global__ void __launch_bounds__(256) gathersum(const float* __restrict__ Y,
                                                 const float* __restrict__ CfT)
{
    __shared__ int4   sid[9];
    __shared__ float4 swt[9];
    __nv_bfloat16* fh = (__nv_bfloat16*)(g_ws + FH_OFF);
    __nv_bfloat16* fl = (__nv_bfloat16*)(g_ws + FL_OFF);
    int pix = blockIdx.x;
    int t   = threadIdx.x;
    if (t < 9) {
        sid[t] = g_idx[t * NPIX + pix];
        swt[t] = g_wt [t * NPIX + pix];
    }
    __syncthreads();
    float acc = CfT[(size_t)pix * 256 + t];
#pragma unroll
    for (int kp = 0; kp < 9; kp++) {
        const float* Yk = Y + (size_t)kp * QPAD * 256;
        int4   id = sid[kp];
        float4 w  = swt[kp];
        acc += w.x * Yk[(size_t)id.x * 256 + t] + w.y * Yk[(size_t)id.y * 256 + t]
             + w.z * Yk[(size_t)id.z * 256 + t] + w.w * Yk[(size_t)id.w * 256 + t];
    }
    __nv_bfloat16 h = __float2bfloat16(acc);
    fh[(size_t)pix * 256 + t] = h;
    fl[(size_t)pix * 256 + t] = __float2bfloat16(acc - __bfloat162float(h));
}

// ---------------- HMMA bf16 split GEMM (2-stage, occupancy 2) ----------------
// EPI 3: relu(x*e1[row]+e2[row]) -> C[m][NPIX]
// EPI 8: EPI3 + transposed bf16 hi/lo planes (Ct, Ct2)
// EPI 5: raw -> transposed fp32 Ct (nbase = zz*nq + bcol)
// EPI 7: raw + bilinear-upsampled Z (e1 = Z base) -> transposed fp32 Ct
// IMC 1: B operand is implicit 3x3 im2col over plane [pix][256]
#define BK        32
#define ASTRIDE   40
#define PLANE_B   (128 * ASTRIDE * 2)      // 10240 B
#define STAGE_B   (4 * PLANE_B)            // 40960 B
#define GEMM_SMEM (2 * STAGE_B)            // 81920 B

template<int IMC>
__device__ __forceinline__ void issue_stage(
    uint32_t sb, int stage, const __nv_bfloat16* __restrict__ pA_h,
    const __nv_bfloat16* __restrict__ pA_l, const __nv_bfloat16* __restrict__ pB_h,
    const __nv_bfloat16* __restrict__ pB_l, int sA, int sB, int k0, int tid, int bcol)
{
    uint32_t stb = sb + stage * STAGE_B;
    int kh = 0, kw = 0, cbase = 0;
    if (IMC) {
        int kp = k0 >> 8;
        kh = kp / 3; kw = kp - kh * 3;
        cbase = k0 & 255;
    }
#pragma unroll
    for (int q = 0; q < 2; q++) {
        int id  = tid * 2 + q;
        int row = id >> 2, seg = id & 3;
        uint32_t doff = (row * ASTRIDE + seg * 8) * 2;
        size_t aoff = (size_t)row * sA + k0 + seg * 8;
        CP_ASYNC16(stb + doff,           pA_h + aoff);
        CP_ASYNC16(stb + PLANE_B + doff, pA_l + aoff);
        if (IMC) {
            int pix = bcol + row;
            int hh = pix >> 7, ww = pix & 127;
            int ih = hh + kh - 1, iw = ww + kw - 1;
            bool ok = ((unsigned)ih < 128u) && ((unsigned)iw < 128u);
            size_t boff = ok ? ((size_t)(ih * 128 + iw) * 256 + cbase + seg * 8) : 0;
            unsigned sz = ok ? 16u : 0u;
            CP_ASYNC16Z(stb + 2 * PLANE_B + doff, pB_h + boff, sz);
            CP_ASYNC16Z(stb + 3 * PLANE_B + doff, pB_l + boff, sz);
        } else {
            size_t boff = (size_t)row * sB + k0 + seg * 8;
            CP_ASYNC16(stb + 2 * PLANE_B + doff, pB_h + boff);
            CP_ASYNC16(stb + 3 * PLANE_B + doff, pB_l + boff);
        }
    }
    CP_COMMIT();
}

template<int EPI, int IMC>
__global__ void __launch_bounds__(256, 2) mma_gemm(
    const __nv_bfloat16* __restrict__ Ah, const __nv_bfloat16* __restrict__ Al,
    const __nv_bfloat16* __restrict__ Bh, const __nv_bfloat16* __restrict__ Bl,
    float* __restrict__ C, void* __restrict__ Ct, void* __restrict__ Ct2,
    int K, int sA, int sB, int nq, int zoff,
    const float* __restrict__ e1, const float* __restrict__ e2)
{
    extern __shared__ char sm[];
    uint32_t sb = smem_u32(sm);
    const int tid = threadIdx.x;
    const int wid = tid >> 5, lane = tid & 31;
    const int wr = wid >> 2, wc = wid & 3;
    const int brow = blockIdx.y * 128, bcol = blockIdx.x * 128;
    const int zz = blockIdx.z;

    const __nv_bfloat16* pA_h = Ah + (size_t)brow * sA + zz * 512 + zoff;
    const __nv_bfloat16* pA_l = Al + (size_t)brow * sA + zz * 512 + zoff;
    const __nv_bfloat16* pB_h = IMC ? Bh : Bh + (size_t)bcol * sB;
    const __nv_bfloat16* pB_l = IMC ? Bl : Bl + (size_t)bcol * sB;

    float acc[4][4][4];
#pragma unroll
    for (int i = 0; i < 4; i++)
#pragma unroll
        for (int j = 0; j < 4; j++)
#pragma unroll
            for (int q = 0; q < 4; q++) acc[i][j][q] = 0.0f;

    const int sub = lane >> 3, rr = lane & 7;
    const int am = wr * 64 + (sub & 1) * 8 + rr;
    const int ak = (sub >> 1) * 8;
    const int bn = wc * 32 + (sub >> 1) * 8 + rr;
    const int bk = (sub & 1) * 8;

    const int NC = K / BK;
    issue_stage<IMC>(sb, 0, pA_h, pA_l, pB_h, pB_l, sA, sB, 0, tid, bcol);
    issue_stage<IMC>(sb, 1, pA_h, pA_l, pB_h, pB_l, sA, sB, BK, tid, bcol);

    for (int ci = 0; ci < NC; ci++) {
        if (ci + 1 < NC) CP_WAIT1(); else CP_WAIT0();
        __syncthreads();

        uint32_t stb = sb + (ci & 1) * STAGE_B;
#pragma unroll
        for (int ks = 0; ks < 2; ks++) {
            uint32_t ah[4][4], al[4][4], bh[4][2], bl[4][2];
#pragma unroll
            for (int mt = 0; mt < 4; mt++) {
                uint32_t aoff = ((am + mt * 16) * ASTRIDE + ks * 16 + ak) * 2;
                ldsm4(ah[mt], stb + aoff);
                ldsm4(al[mt], stb + PLANE_B + aoff);
            }
#pragma unroll
            for (int ntp = 0; ntp < 2; ntp++) {
                uint32_t boff = ((bn + ntp * 16) * ASTRIDE + ks * 16 + bk) * 2;
                uint32_t rh[4], rl[4];
                ldsm4(rh, stb + 2 * PLANE_B + boff);
                ldsm4(rl, stb + 3 * PLANE_B + boff);
                bh[ntp * 2 + 0][0] = rh[0]; bh[ntp * 2 + 0][1] = rh[1];
                bh[ntp * 2 + 1][0] = rh[2]; bh[ntp * 2 + 1][1] = rh[3];
                bl[ntp * 2 + 0][0] = rl[0]; bl[ntp * 2 + 0][1] = rl[1];
                bl[ntp * 2 + 1][0] = rl[2]; bl[ntp * 2 + 1][1] = rl[3];
            }
#pragma unroll
            for (int mt = 0; mt < 4; mt++)
#pragma unroll
                for (int nt = 0; nt < 4; nt++) {
                    mma_bf16(acc[mt][nt], ah[mt], bh[nt][0], bh[nt][1]);
                    mma_bf16(acc[mt][nt], al[mt], bh[nt][0], bh[nt][1]);
                    mma_bf16(acc[mt][nt], ah[mt], bl[nt][0], bl[nt][1]);
                }
        }
        __syncthreads();
        if (ci + 2 < NC)
            issue_stage<IMC>(sb, ci & 1, pA_h, pA_l, pB_h, pB_l, sA, sB,
                             (ci + 2) * BK, tid, bcol);
    }

    // ---------------- epilogue ----------------
    const int gid = lane >> 2, t4 = lane & 3;
    float* smf = (float*)sm;                        // stride 132 -> 67584 B
#pragma unroll
    for (int mt = 0; mt < 4; mt++) {
        int ml = wr * 64 + mt * 16 + gid;
        int m0 = brow + ml;
#pragma unroll
        for (int nt = 0; nt < 4; nt++) {
            int nl = wc * 32 + nt * 8 + t4 * 2;
            int n0 = bcol + nl;
            float v0, v1, v2, v3;
            if (EPI == 5 || EPI == 7) {
                v0 = acc[mt][nt][0]; v1 = acc[mt][nt][1];
                v2 = acc[mt][nt][2]; v3 = acc[mt][nt][3];
            } else {
                float s0 = e1[m0], b0 = e2[m0];
                float s1 = e1[m0 + 8], b1 = e2[m0 + 8];
                v0 = fmaxf(acc[mt][nt][0] * s0 + b0, 0.0f);
                v1 = fmaxf(acc[mt][nt][1] * s0 + b0, 0.0f);
                v2 = fmaxf(acc[mt][nt][2] * s1 + b1, 0.0f);
                v3 = fmaxf(acc[mt][nt][3] * s1 + b1, 0.0f);
                *(float2*)(C + (size_t)m0 * NPIX + n0)       = make_float2(v0, v1);
                *(float2*)(C + (size_t)(m0 + 8) * NPIX + n0) = make_float2(v2, v3);
            }
            if (EPI != 3) {
                smf[(nl)     * 132 + ml]     = v0;
                smf[(nl + 1) * 132 + ml]     = v1;
                smf[(nl)     * 132 + ml + 8] = v2;
                smf[(nl + 1) * 132 + ml + 8] = v3;
            }
        }
    }
    if (EPI == 3) return;
    __syncthreads();

    int4*   sQ = (int4*)(sm + 67584);
    float2* sW = (float2*)(sm + 67584 + 2048);
    if (EPI == 7) {
        if (tid < 128) {
            int q = bcol + tid;
            int4 qq = make_int4(-1, 0, 0, 0);
            float2 ww = make_float2(0.0f, 0.0f);
            if (q < 16900) {
                int i = q / 130, j = q - i * 130;
                if (i >= 1 && i <= 128 && j >= 1 && j <= 128) {
                    int h = i - 1, w = j - 1;
                    float fy = h * (31.0f / 127.0f);
                    float fx = w * (31.0f / 127.0f);
                    int y0 = (int)floorf(fy); int y1 = min(y0 + 1, 31);
                    int x0 = (int)floorf(fx); int x1 = min(x0 + 1, 31);
                    ww = make_float2(fy - (float)y0, fx - (float)x0);
                    qq = make_int4(y0 * 32 + x0, y0 * 32 + x1, y1 * 32 + x0, y1 * 32 + x1);
                }
            }
            sQ[tid] = qq; sW[tid] = ww;
        }
        __syncthreads();
    }

    size_t nbase = (size_t)zz * nq + bcol;
#pragma unroll 4
    for (int i = 0; i < 64; i++) {
        int idx = i * 256 + tid;
        int nl = idx >> 7, ml = idx & 127;
        float v = smf[nl * 132 + ml];
        if (EPI == 7) {
            int4 qq = sQ[nl];
            if (qq.x >= 0) {
                float2 ww = sW[nl];
                const float* Zk = e1 + (size_t)zz * 262144;
                int o = brow + ml;
                float r0 = Zk[qq.x * 256 + o] * (1.0f - ww.x) + Zk[qq.z * 256 + o] * ww.x;
                float r1 = Zk[qq.y * 256 + o] * (1.0f - ww.x) + Zk[qq.w * 256 + o] * ww.x;
                v += r0 * (1.0f - ww.y) + r1 * ww.y;
            }
        }
        if (EPI == 5 || EPI == 7) {
            ((float*)Ct)[(nbase + nl) * 256 + brow + ml] = v;
        } else {   // EPI 8
            __nv_bfloat16 hh = __float2bfloat16(v);
            ((__nv_bfloat16*)Ct )[(nbase + nl) * 256 + brow + ml] = hh;
            ((__nv_bfloat16*)Ct2)[(nbase + nl) * 256 + brow + ml] =
                __float2bfloat16(v - __bfloat162float(hh));
        }
    }
}

// ---------------- host launcher ----------------
extern "C" void kernel_launch(void* const* d_in, const int* in_sizes, int n_in,
                              void* d_out, int out_size)
{
    (void)in_sizes; (void)n_in; (void)out_size;
    const float* x    = (const float*)d_in[0];
    const float* llf  = (const float*)d_in[1];
    const float* fm_w = (const float*)d_in[2];
    const float* fs_w = (const float*)d_in[3];
    const float* p_w  = (const float*)d_in[4];
    const float* p_b  = (const float*)d_in[5];
    const float* dc_w = (const float*)d_in[6];
    const float* lc1w = (const float*)d_in[7];
    const float* g1 = (const float*)d_in[8],  *b1 = (const float*)d_in[9];
    const float* m1 = (const float*)d_in[10], *v1 = (const float*)d_in[11];
    const float* lc2w = (const float*)d_in[12];
    const float* g2 = (const float*)d_in[13], *b2 = (const float*)d_in[14];
    const float* m2 = (const float*)d_in[15], *v2 = (const float*)d_in[16];
    float* out = (float*)d_out;

    float *cc, *vv, *uu, *bns, *bnb;
    __nv_bfloat16 *Ah, *Al, *cbh, *cbl, *xbh, *xbl;
    char* ws;
    cudaGetSymbolAddress((void**)&cc,  g_cc);
    cudaGetSymbolAddress((void**)&vv,  g_v);
    cudaGetSymbolAddress((void**)&uu,  g_u);
    cudaGetSymbolAddress((void**)&bns, g_bnscale);
    cudaGetSymbolAddress((void**)&bnb, g_bnbias);
    cudaGetSymbolAddress((void**)&Ah,  g_Ah);
    cudaGetSymbolAddress((void**)&Al,  g_Al);
    cudaGetSymbolAddress((void**)&cbh, g_cbh);
    cudaGetSymbolAddress((void**)&cbl, g_cbl);
    cudaGetSymbolAddress((void**)&xbh, g_xbh);
    cudaGetSymbolAddress((void**)&xbl, g_xbl);
    cudaGetSymbolAddress((void**)&ws,  g_ws);
    float* Y = (float*)ws;
    float* Z = uu;                                  // reuse g_u after Cf is done
    __nv_bfloat16* fh  = (__nv_bfloat16*)(ws + FH_OFF);
    __nv_bfloat16* fl  = (__nv_bfloat16*)(ws + FL_OFF);
    __nv_bfloat16* u1h = (__nv_bfloat16*)(ws + U1H_OFF);
    __nv_bfloat16* u1l = (__nv_bfloat16*)(ws + U1L_OFF);

    cudaFuncSetAttribute(mma_gemm<3,1>, cudaFuncAttributeMaxDynamicSharedMemorySize, GEMM_SMEM);
    cudaFuncSetAttribute(mma_gemm<8,1>, cudaFuncAttributeMaxDynamicSharedMemorySize, GEMM_SMEM);
    cudaFuncSetAttribute(mma_gemm<5,0>, cudaFuncAttributeMaxDynamicSharedMemorySize, GEMM_SMEM);
    cudaFuncSetAttribute(mma_gemm<7,0>, cudaFuncAttributeMaxDynamicSharedMemorySize, GEMM_SMEM);

    // 1. BN coefficients + permuted weight splits + x transpose
    bncoef_k<<<1, 512>>>(g1, b1, m1, v1, g2, b2, m2, v2);
    split_perm<<<(1179648 + 255) / 256, 256>>>(dc_w, Ah, Al, 512, 1179648);
    split_perm<<<(589824 + 255) / 256, 256>>>(lc1w, Ah + 1179648, Al + 1179648, 256, 589824);
    split_perm<<<(589824 + 255) / 256, 256>>>(lc2w, Ah + 1769472, Al + 1769472, 256, 589824);
    transpose_x_bf<<<dim3(32, 8), dim3(32, 8)>>>(x);
    // 2. xu -> cc[0:256]
    upsample_k<<<NPIX, 256>>>(x);
    // 3. v = sigmoid(fm_w @ llf)
    sgemm_epi<1><<<dim3(128, 2), 256>>>(fm_w, llf, vv, nullptr, 256);
    // 4. u[c] = llf[c] @ v[c] + llf[c]
    chan_matmul<<<256, 256>>>(llf);
    // 5. Cf = fs_w @ u -> cc[256:512] (+ CfT -> g_v)
    sgemm_epi<6><<<dim3(128, 2), 256>>>(fs_w, uu, cc + (size_t)256 * NPIX, vv, 256);
    // 6. offsets = p_w @ im2col(cc) + p_b
    gemm_off<<<NPIX / 128, 512>>>(p_w, p_b);
    // 7. Cf pad+transpose -> bf16 hi/lo
    border_zero_cf<<<(516 * 256 + 255) / 256, 256>>>();
    transpose_pad_cf<<<dim3(128, 4, 8), dim3(32, 8)>>>();
    // 8. bilinear coords/weights
    coords_k<<<9 * NPIX / 256, 256>>>();
    // 9. Z[kp] = (dc_w_xu_kp @ x32^T)^T  (tiny GEMM, 1024 cols)
    mma_gemm<5,0><<<dim3(8, 2, 9), 256, GEMM_SMEM>>>(
        Ah, Al, xbh, xbl, nullptr, Z, nullptr, 256, 4608, 256, 1024, 0,
        nullptr, nullptr);
    // 10. Y[kp] = (dc_w_cf_kp @ Cfp^T)^T + upsample(Z[kp])
    mma_gemm<7,0><<<dim3(QPAD / 128, 2, 9), 256, GEMM_SMEM>>>(
        Ah, Al, cbh, cbl, nullptr, Y, nullptr, 256, 4608, 256, QPAD, 256,
        Z, nullptr);
    // 11. famT = gathersum(Y) + CfT -> bf16 hi/lo planes
    gathersum<<<NPIX, 256>>>(Y, vv);
    // 12. up1 = relu(bn1(lc1 (*) fam)) -> out + up1T hi/lo planes (implicit im2col)
    mma_gemm<8,1><<<dim3(128, 2), 256, GEMM_SMEM>>>(
        Ah + 1179648, Al + 1179648, fh, fl, out, u1h, u1l, 2304, 2304, 0, NPIX, 0,
        bns, bnb);
    // 13. up2 = relu(bn2(lc2 (*) up1)) -> out[256*NPIX:] (implicit im2col)
    mma_gemm<3,1><<<dim3(128, 2), 256, GEMM_SMEM>>>(
        Ah + 1769472, Al + 1769472, u1h, u1l, out + (size_t)256 * NPIX, nullptr, nullptr,
        2304, 2304, 0, NPIX, 0, bns + 256, bnb + 256);
}

// round 8
// speedup vs baseline: 3.0463x; 1.1512x over previous
#include <cuda_runtime.h>
#include <cuda_bf16.h>
#include <cuda_fp16.h>
#include <math.h>
#include <stdint.h>

#define NPIX 16384          // 128*128
#define QPAD 17024          // 16900 padded positions rounded up to 128 multiple

// ---------------- static device scratch (no allocations allowed) ----------------
__device__ __align__(16) float  g_cc  [512 * NPIX];          // [xu(256) ; Cf(256)] chan-major
__device__ __align__(16) float  g_v   [256 * NPIX];          // v; then CfT
__device__ __align__(16) float  g_u   [256 * NPIX];          // u; then Z[9][1024][256]
__device__ __align__(16) float  g_off [ 18 * NPIX];
__device__ __align__(16) int4   g_idx [9 * NPIX];
__device__ __align__(16) float4 g_wt  [9 * NPIX];
__device__ __align__(16) float  g_bnscale[512];
__device__ __align__(16) float  g_bnbias [512];
// fp16 single-plane operands
__device__ __align__(16) __half g_cfh[QPAD * 256];           // padded Cf map [q][256]
__device__ __align__(16) __half g_xh [1024 * 256];           // x32 transposed [s][256]
// workspace: Y[9][QPAD][256] fp32, then famT / up1T fp16 planes
#define Y_BYTES   ((size_t)9 * QPAD * 256 * 4)
#define PLANE_SZ  ((size_t)NPIX * 256 * 2)
#define FH_OFF    (Y_BYTES)
#define U1H_OFF   (Y_BYTES + PLANE_SZ)
__device__ __align__(16) char g_ws[Y_BYTES + 2 * PLANE_SZ];
// fp16 hi/lo weight planes (k-permuted): dc @0, lc1 @1179648, lc2 @1769472
__device__ __align__(16) __half g_Ah[2359296];
__device__ __align__(16) __half g_Al[2359296];

// ---------------- PTX helpers (baseline compute_103 ISA only) ----------------
__device__ __forceinline__ uint32_t smem_u32(const void* p) {
    uint32_t a;
    asm("{ .reg .u64 t; cvta.to.shared.u64 t, %1; cvt.u32.u64 %0, t; }" : "=r"(a) : "l"(p));
    return a;
}
#define CP_ASYNC16(dst, src) \
    asm volatile("cp.async.cg.shared.global [%0], [%1], 16;" :: "r"(dst), "l"(src))
#define CP_ASYNC16Z(dst, src, sz) \
    asm volatile("cp.async.cg.shared.global [%0], [%1], 16, %2;" :: "r"(dst), "l"(src), "r"(sz))
#define CP_COMMIT() asm volatile("cp.async.commit_group;")
#define CP_WAIT2()  asm volatile("cp.async.wait_group 2;" ::: "memory")
#define CP_WAIT1()  asm volatile("cp.async.wait_group 1;" ::: "memory")
#define CP_WAIT0()  asm volatile("cp.async.wait_group 0;" ::: "memory")

__device__ __forceinline__ void ldsm4(uint32_t r[4], uint32_t addr) {
    asm volatile("ldmatrix.sync.aligned.m8n8.x4.shared.b16 {%0,%1,%2,%3}, [%4];"
                 : "=r"(r[0]), "=r"(r[1]), "=r"(r[2]), "=r"(r[3]) : "r"(addr));
}
__device__ __forceinline__ void mma_f16(float c[4], const uint32_t a[4],
                                        uint32_t b0, uint32_t b1) {
    asm volatile("mma.sync.aligned.m16n8k16.row.col.f32.f16.f16.f32 "
                 "{%0,%1,%2,%3}, {%4,%5,%6,%7}, {%8,%9}, {%0,%1,%2,%3};"
                 : "+f"(c[0]), "+f"(c[1]), "+f"(c[2]), "+f"(c[3])
                 : "r"(a[0]), "r"(a[1]), "r"(a[2]), "r"(a[3]), "r"(b0), "r"(b1));
}

// ---------------- BN coefficient precompute ----------------
__global__ void bncoef_k(const float* __restrict__ g1, const float* __restrict__ b1,
                         const float* __restrict__ m1, const float* __restrict__ v1,
                         const float* __restrict__ g2, const float* __restrict__ b2,
                         const float* __restrict__ m2, const float* __restrict__ v2)
{
    int i = threadIdx.x;
    if (i < 256) {
        float s = g1[i] / sqrtf(v1[i] + 1e-5f);
        g_bnscale[i] = s;
        g_bnbias[i]  = b1[i] - m1[i] * s;
    } else {
        int j = i - 256;
        float s = g2[j] / sqrtf(v2[j] + 1e-5f);
        g_bnscale[i] = s;
        g_bnbias[i]  = b2[j] - m2[j] * s;
    }
}

// ---------------- weight fp16 hi/lo split with K permutation: k = kp*C + c ----------------
__global__ void split_perm(const float* __restrict__ w, __half* __restrict__ hi,
                           __half* __restrict__ lo, int C, int n)
{
    int t = blockIdx.x * 256 + threadIdx.x;
    if (t >= n) return;
    int K = C * 9;
    int o = t / K, r = t - o * K;
    int c = r / 9, kp = r - c * 9;
    int dst = o * K + kp * C + c;
    float v = w[t];
    __half h = __float2half(v);
    hi[dst] = h;
    lo[dst] = __float2half(v - __half2float(h));
}

// ---------------- bilinear upsample 32x32 -> 128x128, align_corners=True ----------------
__global__ void upsample_k(const float* __restrict__ x)
{
    int t = blockIdx.x * 256 + threadIdx.x;
    int pix = t & (NPIX - 1);
    int c   = t >> 14;
    int oy = pix >> 7, ox = pix & 127;
    const float s = 31.0f / 127.0f;
    float fy = oy * s, fx = ox * s;
    int y0 = (int)floorf(fy); int y1 = min(y0 + 1, 31);
    int x0 = (int)floorf(fx); int x1 = min(x0 + 1, 31);
    float wy = fy - (float)y0;
    float wx = fx - (float)x0;
    const float* xc = x + c * 1024;
    float v00 = xc[y0 * 32 + x0], v01 = xc[y0 * 32 + x1];
    float v10 = xc[y1 * 32 + x0], v11 = xc[y1 * 32 + x1];
    float r0 = v00 * (1.0f - wy) + v10 * wy;
    float r1 = v01 * (1.0f - wy) + v11 * wy;
    g_cc[t] = r0 * (1.0f - wx) + r1 * wx;
}

// ---------------- transpose x: x[c][s] -> xh[s][256] fp16 ----------------
__global__ void transpose_x_h(const float* __restrict__ x)
{
    __shared__ float sm[32][33];
    int s0 = blockIdx.x * 32, c0 = blockIdx.y * 32;
    int tx = threadIdx.x, ty = threadIdx.y;     // 32 x 8
#pragma unroll
    for (int i = 0; i < 4; i++)
        sm[ty + 8 * i][tx] = x[(c0 + ty + 8 * i) * 1024 + s0 + tx];
    __syncthreads();
#pragma unroll
    for (int i = 0; i < 4; i++)
        g_xh[(s0 + ty + 8 * i) * 256 + c0 + tx] = __float2half(sm[tx][ty + 8 * i]);
}

// ---------------- FFMA SGEMM for the two small K=256 GEMMs ----------------
// EPI: 1 sigmoid, 6 none + transposed copy Ct[n][256]
template<int EPI>
__global__ void __launch_bounds__(256, 2) sgemm_epi(
    const float* __restrict__ A, const float* __restrict__ B, float* __restrict__ C,
    float* __restrict__ Ct, int K)
{
    __shared__ float As[16][128];
    __shared__ float Bs[16][128];
    const int tid  = threadIdx.x;
    const int brow = blockIdx.y * 128;
    const int bcol = blockIdx.x * 128;
    const int ty = tid >> 4, tx = tid & 15;

    float acc[8][8];
#pragma unroll
    for (int i = 0; i < 8; i++)
#pragma unroll
        for (int j = 0; j < 8; j++) acc[i][j] = 0.0f;

    for (int k0 = 0; k0 < K; k0 += 16) {
#pragma unroll
        for (int l = 0; l < 2; l++) {
            int f = tid + l * 256;
            int ar = f >> 2, akq = f & 3;
            float4 av = *(const float4*)(A + (size_t)(brow + ar) * K + k0 + akq * 4);
            As[akq * 4 + 0][ar] = av.x;
            As[akq * 4 + 1][ar] = av.y;
            As[akq * 4 + 2][ar] = av.z;
            As[akq * 4 + 3][ar] = av.w;
            int bkr = f >> 5, bcq = f & 31;
            *(float4*)(&Bs[bkr][bcq * 4]) =
                *(const float4*)(B + (size_t)(k0 + bkr) * NPIX + bcol + bcq * 4);
        }
        __syncthreads();
#pragma unroll
        for (int kk = 0; kk < 16; kk++) {
            float ra[8], rb[8];
#pragma unroll
            for (int i = 0; i < 8; i++) ra[i] = As[kk][ty * 8 + i];
#pragma unroll
            for (int j = 0; j < 8; j++) rb[j] = Bs[kk][tx * 8 + j];
#pragma unroll
            for (int i = 0; i < 8; i++)
#pragma unroll
                for (int j = 0; j < 8; j++)
                    acc[i][j] = fmaf(ra[i], rb[j], acc[i][j]);
        }
        __syncthreads();
    }
#pragma unroll
    for (int i = 0; i < 8; i++) {
        int row = brow + ty * 8 + i;
#pragma unroll
        for (int j = 0; j < 8; j++) {
            int col = bcol + tx * 8 + j;
            float v = acc[i][j];
            if (EPI == 1) v = 1.0f / (1.0f + expf(-v));
            C[(size_t)row * NPIX + col] = v;
        }
    }
    if (EPI == 6) {
#pragma unroll
        for (int j = 0; j < 8; j++) {
            int col = bcol + tx * 8 + j;
            float4 a = make_float4(acc[0][j], acc[1][j], acc[2][j], acc[3][j]);
            float4 b = make_float4(acc[4][j], acc[5][j], acc[6][j], acc[7][j]);
            *(float4*)(Ct + (size_t)col * 256 + brow + ty * 8)     = a;
            *(float4*)(Ct + (size_t)col * 256 + brow + ty * 8 + 4) = b;
        }
    }
}

// ---------------- per-channel 128x128x128 matmul: u[c] = llf[c] @ v[c] + llf[c] ----------------
__global__ void __launch_bounds__(256, 2) chan_matmul(const float* __restrict__ llf)
{
    const int c = blockIdx.x;
    const float* A = llf + (size_t)c * NPIX;
    const float* B = g_v + (size_t)c * NPIX;
    float*       C = g_u + (size_t)c * NPIX;

    __shared__ float As[16][128];
    __shared__ float Bs[16][128];
    const int tid = threadIdx.x;
    const int ty = tid >> 4, tx = tid & 15;

    float acc[8][8];
#pragma unroll
    for (int i = 0; i < 8; i++)
#pragma unroll
        for (int j = 0; j < 8; j++) acc[i][j] = 0.0f;

    for (int k0 = 0; k0 < 128; k0 += 16) {
#pragma unroll
        for (int l = 0; l < 2; l++) {
            int f = tid + l * 256;
            int ar = f >> 2, akq = f & 3;
            float4 av = *(const float4*)(A + ar * 128 + k0 + akq * 4);
            As[akq * 4 + 0][ar] = av.x;
            As[akq * 4 + 1][ar] = av.y;
            As[akq * 4 + 2][ar] = av.z;
            As[akq * 4 + 3][ar] = av.w;
            int bkr = f >> 5, bcq = f & 31;
            *(float4*)(&Bs[bkr][bcq * 4]) = *(const float4*)(B + (k0 + bkr) * 128 + bcq * 4);
        }
        __syncthreads();
#pragma unroll
        for (int kk = 0; kk < 16; kk++) {
            float ra[8], rb[8];
#pragma unroll
            for (int i = 0; i < 8; i++) ra[i] = As[kk][ty * 8 + i];
#pragma unroll
            for (int j = 0; j < 8; j++) rb[j] = Bs[kk][tx * 8 + j];
#pragma unroll
            for (int i = 0; i < 8; i++)
#pragma unroll
                for (int j = 0; j < 8; j++)
                    acc[i][j] = fmaf(ra[i], rb[j], acc[i][j]);
        }
        __syncthreads();
    }
#pragma unroll
    for (int i = 0; i < 8; i++) {
        int row = ty * 8 + i;
#pragma unroll
        for (int j = 0; j < 8; j++) {
            int col = tx * 8 + j;
            C[row * 128 + col] = acc[i][j] + A[row * 128 + col];
        }
    }
}

// ---------------- offsets conv (implicit im2col): off = p_w(18x4608) @ im2col(cc) + p_b ----
__global__ void __launch_bounds__(512) gemm_off(const float* __restrict__ A,
                                                const float* __restrict__ bias)
{
    const int K = 4608, KG = 1152;
    __shared__ float Ash[4][16][18];
    __shared__ float red[4][18][128];
    int tid  = threadIdx.x;
    int g    = tid >> 7;
    int lane = tid & 127;
    int pix  = blockIdx.x * 128 + lane;
    int h = pix >> 7, w = pix & 127;

    float acc[18];
#pragma unroll
    for (int o = 0; o < 18; o++) acc[o] = 0.0f;

    for (int kc = 0; kc < KG; kc += 16) {
        int k0 = g * KG + kc;
        for (int i = lane; i < 288; i += 128) {
            int o = i / 16, kk = i % 16;
            Ash[g][kk][o] = A[o * K + k0 + kk];
        }
        __syncthreads();
#pragma unroll 4
        for (int kk = 0; kk < 16; kk++) {
            int k = k0 + kk;
            int c = k / 9, r = k - c * 9;
            int kh = r / 3, kw = r - kh * 3;
            int ih = h + kh - 1, iw = w + kw - 1;
            float b = 0.0f;
            if ((unsigned)ih < 128u && (unsigned)iw < 128u)
                b = g_cc[((size_t)c << 14) + (ih << 7) + iw];
#pragma unroll
            for (int o = 0; o < 18; o++) acc[o] = fmaf(Ash[g][kk][o], b, acc[o]);
        }
        __syncthreads();
    }
#pragma unroll
    for (int o = 0; o < 18; o++) red[g][o][lane] = acc[o];
    __syncthreads();
    if (g == 0) {
#pragma unroll
        for (int o = 0; o < 18; o++) {
            float s = red[0][o][lane] + red[1][o][lane] + red[2][o][lane] + red[3][o][lane]
                    + bias[o];
            g_off[o * NPIX + pix] = s;
        }
    }
}

// ---------------- zero border rows of cfh ----------------
__global__ void border_zero_cf()
{
    int t = blockIdx.x * 256 + threadIdx.x;       // 516 * 256
    if (t >= 516 * 256) return;
    int b = t >> 8, c = t & 255;
    int q;
    if (b < 130)       q = b;
    else if (b < 260)  q = 129 * 130 + (b - 130);
    else {
        int r = b - 260;
        int hh = 1 + (r >> 1);
        int ww = (r & 1) ? 129 : 0;
        q = hh * 130 + ww;
    }
    g_cfh[(size_t)q * 256 + c] = __float2half(0.0f);
}

// ---------------- transpose+pad Cf: cc[256+c][pix] -> cfh[(h+1)*130+w+1][c] fp16 --------
__global__ void transpose_pad_cf()
{
    __shared__ float sm[32][33];
    int h  = blockIdx.x;
    int w0 = blockIdx.y * 32;
    int c0 = blockIdx.z * 32;
    int tx = threadIdx.x, ty = threadIdx.y;   // 32 x 8
#pragma unroll
    for (int i = 0; i < 4; i++)
        sm[ty + 8 * i][tx] =
            g_cc[(size_t)(256 + c0 + ty + 8 * i) * NPIX + h * 128 + w0 + tx];
    __syncthreads();
#pragma unroll
    for (int i = 0; i < 4; i++)
        g_cfh[(size_t)((h + 1) * 130 + (w0 + ty + 8 * i + 1)) * 256 + c0 + tx] =
            __float2half(sm[tx][ty + 8 * i]);
}

// ---------------- deform sampling coords + bilinear weights ----------------
__global__ void coords_k()
{
    int t = blockIdx.x * 256 + threadIdx.x;        // 9*NPIX, layout [k][pix]
    int pix = t & (NPIX - 1);
    int k   = t >> 14;
    int h = pix >> 7, w = pix & 127;
    float pnx = (float)(k / 3 - 1);
    float pny = (float)(k % 3 - 1);
    float px = g_off[k * NPIX + pix]       + pnx + (float)(h + 1);
    float py = g_off[(9 + k) * NPIX + pix] + pny + (float)(w + 1);
    float fx = floorf(px), fy = floorf(py);
    float x0 = fminf(fmaxf(fx,        0.0f), 129.0f);
    float x1 = fminf(fmaxf(fx + 1.0f, 0.0f), 129.0f);
    float y0 = fminf(fmaxf(fy,        0.0f), 129.0f);
    float y1 = fminf(fmaxf(fy + 1.0f, 0.0f), 129.0f);
    float pxc = fminf(fmaxf(px, 0.0f), 129.0f);
    float pyc = fminf(fmaxf(py, 0.0f), 129.0f);
    float glt = (1.0f + (x0 - pxc)) * (1.0f + (y0 - pyc));
    float grb = (1.0f - (x1 - pxc)) * (1.0f - (y1 - pyc));
    float glb = (1.0f + (x0 - pxc)) * (1.0f - (y1 - pyc));
    float grt = (1.0f - (x1 - pxc)) * (1.0f + (y0 - pyc));
    int ix0 = (int)x0, ix1 = (int)x1, iy0 = (int)y0, iy1 = (int)y1;
    g_idx[t] = make_int4(ix0 * 130 + iy0, ix1 * 130 + iy1, ix0 * 130 + iy1, ix1 * 130 + iy0);
    g_wt[t]  = make_float4(glt, grb, glb, grt);
}

// ---------------- gather-sum -> famT fp16 plane ----------------
__global__ void __launch_bounds__(256) gathersum(const float* __restrict__ Y,
                                                 const float* __restrict__ CfT)
{
    __shared__ int4   sid[9];
    __shared__ float4 swt[9];
    __half* fh = (__half*)(g_ws + FH_OFF);
    int pix = blockIdx.x;
    int t   = threadIdx.x;
    if (t < 9) {
        sid[t] = g_idx[t * NPIX + pix];
        swt[t] = g_wt [t * NPIX + pix];
    }
    __syncthreads();
    float acc = CfT[(size_t)pix * 256 + t];
#pragma unroll
    for (int kp = 0; kp < 9; kp++) {
        const float* Yk = Y + (size_t)kp * QPAD * 256;
        int4   id = sid[kp];
        float4 w  = swt[kp];
        acc += w.x * Yk[(size_t)id.x * 256 + t] + w.y * Yk[(size_t)id.y * 256 + t]
             + w.z * Yk[(size_t)id.z * 256 + t] + w.w * Yk[(size_t)id.w * 256 + t];
    }
    fh[(size_t)pix * 256 + t] = __float2half(acc);
}

// ---------------- HMMA fp16 2-term GEMM (3-stage, occupancy 2) ----------------
// D = (Ah + Al) @ B, fp32 accum; A fp16 hi/lo (exact), B single fp16 plane.
// EPI 3: relu(x*e1[row]+e2[row]) -> C[m][NPIX]
// EPI 8: EPI3 + transposed fp16 plane Ct
// EPI 5: raw -> transposed fp32 Ct (nbase = zz*nq + bcol)
// EPI 7: raw + bilinear-upsampled Z (e1 = Z base) -> transposed fp32 Ct
// IMC 1: B operand is implicit 3x3 im2col over plane [pix][256]
#define BK        32
#define ASTRIDE   40
#define PLANE_B   (128 * ASTRIDE * 2)      // 10240 B
#define STAGE_B   (3 * PLANE_B)            // Ah, Al, B = 30720 B
#define GEMM_SMEM (3 * STAGE_B)            // 92160 B

template<int IMC>
__device__ __forceinline__ void issue_stage(
    uint32_t sb, int stage, const __half* __restrict__ pA_h,
    const __half* __restrict__ pA_l, const __half* __restrict__ pB,
    int sA, int sB, int k0, int tid, int bcol)
{
    uint32_t stb = sb + stage * STAGE_B;
    int kh = 0, kw = 0, cbase = 0;
    if (IMC) {
        int kp = k0 >> 8;
        kh = kp / 3; kw = kp - kh * 3;
        cbase = k0 & 255;
    }
#pragma unroll
    for (int q = 0; q < 2; q++) {
        int id  = tid * 2 + q;
        int row = id >> 2, seg = id & 3;
        uint32_t doff = (row * ASTRIDE + seg * 8) * 2;
        size_t aoff = (size_t)row * sA + k0 + seg * 8;
        CP_ASYNC16(stb + doff,           pA_h + aoff);
        CP_ASYNC16(stb + PLANE_B + doff, pA_l + aoff);
        if (IMC) {
            int pix = bcol + row;
            int hh = pix >> 7, ww = pix & 127;
            int ih = hh + kh - 1, iw = ww + kw - 1;
            bool ok = ((unsigned)ih < 128u) && ((unsigned)iw < 128u);
            size_t boff = ok ? ((size_t)(ih * 128 + iw) * 256 + cbase + seg * 8) : 0;
            unsigned sz = ok ? 16u : 0u;
            CP_ASYNC16Z(stb + 2 * PLANE_B + doff, pB + boff, sz);
        } else {
            CP_ASYNC16(stb + 2 * PLANE_B + doff, pB + (size_t)row * sB + k0 + seg * 8);
        }
    }
    CP_COMMIT();
}

template<int EPI, int IMC>
__global__ void __launch_bounds__(256, 2) mma_gemm(
    const __half* __restrict__ Ah, const __half* __restrict__ Al,
    const __half* __restrict__ B,
    float* __restrict__ C, void* __restrict__ Ct,
    int K, int sA, int sB, int nq, int zoff,
    const float* __restrict__ e1, const float* __restrict__ e2)
{
    extern __shared__ char sm[];
    uint32_t sb = smem_u32(sm);
    const int tid = threadIdx.x;
    const int wid = tid >> 5, lane = tid & 31;
    const int wr = wid >> 2, wc = wid & 3;
    const int brow = blockIdx.y * 128, bcol = blockIdx.x * 128;
    const int zz = blockIdx.z;

    const __half* pA_h = Ah + (size_t)brow * sA + zz * 512 + zoff;
    const __half* pA_l = Al + (size_t)brow * sA + zz * 512 + zoff;
    const __half* pB   = IMC ? B : B + (size_t)bcol * sB;

    float acc[4][4][4];
#pragma unroll
    for (int i = 0; i < 4; i++)
#pragma unroll
        for (int j = 0; j < 4; j++)
#pragma unroll
            for (int q = 0; q < 4; q++) acc[i][j][q] = 0.0f;

    const int sub = lane >> 3, rr = lane & 7;
    const int am = wr * 64 + (sub & 1) * 8 + rr;
    const int ak = (sub >> 1) * 8;
    const int bn = wc * 32 + (sub >> 1) * 8 + rr;
    const int bk = (sub & 1) * 8;

    const int NC = K / BK;
    issue_stage<IMC>(sb, 0, pA_h, pA_l, pB, sA, sB, 0, tid, bcol);
    issue_stage<IMC>(sb, 1, pA_h, pA_l, pB, sA, sB, BK, tid, bcol);

    for (int ci = 0; ci < NC; ci++) {
        if (ci + 2 < NC) {
            issue_stage<IMC>(sb, (ci + 2) % 3, pA_h, pA_l, pB, sA, sB,
                             (ci + 2) * BK, tid, bcol);
            CP_WAIT2();
        } else if (ci + 1 < NC) {
            CP_WAIT1();
        } else {
            CP_WAIT0();
        }
        __syncthreads();

        uint32_t stb = sb + (ci % 3) * STAGE_B;
#pragma unroll
        for (int ks = 0; ks < 2; ks++) {
            uint32_t ah[4][4], al[4][4], bh[4][2];
#pragma unroll
            for (int mt = 0; mt < 4; mt++) {
                uint32_t aoff = ((am + mt * 16) * ASTRIDE + ks * 16 + ak) * 2;
                ldsm4(ah[mt], stb + aoff);
                ldsm4(al[mt], stb + PLANE_B + aoff);
            }
#pragma unroll
            for (int ntp = 0; ntp < 2; ntp++) {
                uint32_t boff = ((bn + ntp * 16) * ASTRIDE + ks * 16 + bk) * 2;
                uint32_t rh[4];
                ldsm4(rh, stb + 2 * PLANE_B + boff);
                bh[ntp * 2 + 0][0] = rh[0]; bh[ntp * 2 + 0][1] = rh[1];
                bh[ntp * 2 + 1][0] = rh[2]; bh[ntp * 2 + 1][1] = rh[3];
            }
#pragma unroll
            for (int mt = 0; mt < 4; mt++)
#pragma unroll
                for (int nt = 0; nt < 4; nt++) {
                    mma_f16(acc[mt][nt], ah[mt], bh[nt][0], bh[nt][1]);
                    mma_f16(acc[mt][nt], al[mt], bh[nt][0], bh[nt][1]);
                }
        }
        __syncthreads();
    }

    // ---------------- epilogue ----------------
    const int gid = lane >> 2, t4 = lane & 3;
    float* smf = (float*)sm;                        // stride 132 -> 67584 B
#pragma unroll
    for (int mt = 0; mt < 4; mt++) {
        int ml = wr * 64 + mt * 16 + gid;
        int m0 = brow + ml;
#pragma unroll
        for (int nt = 0; nt < 4; nt++) {
            int nl = wc * 32 + nt * 8 + t4 * 2;
            int n0 = bcol + nl;
            float v0, v1, v2, v3;
            if (EPI == 5 || EPI == 7) {
                v0 = acc[mt][nt][0]; v1 = acc[mt][nt][1];
                v2 = acc[mt][nt][2]; v3 = acc[mt][nt][3];
            } else {
                float s0 = e1[m0], b0 = e2[m0];
                float s1 = e1[m0 + 8], b1 = e2[m0 + 8];
                v0 = fmaxf(acc[mt][nt][0] * s0 + b0, 0.0f);
                v1 = fmaxf(acc[mt][nt][1] * s0 + b0, 0.0f);
                v2 = fmaxf(acc[mt][nt][2] * s1 + b1, 0.0f);
                v3 = fmaxf(acc[mt][nt][3] * s1 + b1, 0.0f);
                *(float2*)(C + (size_t)m0 * NPIX + n0)       = make_float2(v0, v1);
                *(float2*)(C + (size_t)(m0 + 8) * NPIX + n0) = make_float2(v2, v3);
            }
            if (EPI != 3) {
                smf[(nl)     * 132 + ml]     = v0;
                smf[(nl + 1) * 132 + ml]     = v1;
                smf[(nl)     * 132 + ml + 8] = v2;
                smf[(nl + 1) * 132 + ml + 8] = v3;
            }
        }
    }
    if (EPI == 3) return;
    __syncthreads();

    int4*   sQ = (int4*)(sm + 67584);
    float2* sW = (float2*)(sm + 67584 + 2048);
    if (EPI == 7) {
        if (tid < 128) {
            int q = bcol + tid;
            int4 qq = make_int4(-1, 0, 0, 0);
            float2 ww = make_float2(0.0f, 0.0f);
            if (q < 16900) {
                int i = q / 130, j = q - i * 130;
                if (i >= 1 && i <= 128 && j >= 1 && j <= 128) {
                    int h = i - 1, w = j - 1;
                    float fy = h * (31.0f / 127.0f);
                    float fx = w * (31.0f / 127.0f);
                    int y0 = (int)floorf(fy); int y1 = min(y0 + 1, 31);
                    int x0 = (int)floorf(fx); int x1 = min(x0 + 1, 31);
                    ww = make_float2(fy - (float)y0, fx - (float)x0);
                    qq = make_int4(y0 * 32 + x0, y0 * 32 + x1, y1 * 32 + x0, y1 * 32 + x1);
                }
            }
            sQ[tid] = qq; sW[tid] = ww;
        }
        __syncthreads();
    }

    size_t nbase = (size_t)zz * nq + bcol;
#pragma unroll 4
    for (int i = 0; i < 64; i++) {
        int idx = i * 256 + tid;
        int nl = idx >> 7, ml = idx & 127;
        float v = smf[nl * 132 + ml];
        if (EPI == 7) {
            int4 qq = sQ[nl];
            if (qq.x >= 0) {
                float2 ww = sW[nl];
                const float* Zk = e1 + (size_t)zz * 262144;
                int o = brow + ml;
                float r0 = Zk[qq.x * 256 + o] * (1.0f - ww.x) + Zk[qq.z * 256 + o] * ww.x;
                float r1 = Zk[qq.y * 256 + o] * (1.0f - ww.x) + Zk[qq.w * 256 + o] * ww.x;
                v += r0 * (1.0f - ww.y) + r1 * ww.y;
            }
        }
        if (EPI == 5 || EPI == 7) {
            ((float*)Ct)[(nbase + nl) * 256 + brow + ml] = v;
        } else {   // EPI 8
            ((__half*)Ct)[(nbase + nl) * 256 + brow + ml] = __float2half(v);
        }
    }
}

// ---------------- host launcher ----------------
extern "C" void kernel_launch(void* const* d_in, const int* in_sizes, int n_in,
                              void* d_out, int out_size)
{
    (void)in_sizes; (void)n_in; (void)out_size;
    const float* x    = (const float*)d_in[0];
    const float* llf  = (const float*)d_in[1];
    const float* fm_w = (const float*)d_in[2];
    const float* fs_w = (const float*)d_in[3];
    const float* p_w  = (const float*)d_in[4];
    const float* p_b  = (const float*)d_in[5];
    const float* dc_w = (const float*)d_in[6];
    const float* lc1w = (const float*)d_in[7];
    const float* g1 = (const float*)d_in[8],  *b1 = (const float*)d_in[9];
    const float* m1 = (const float*)d_in[10], *v1 = (const float*)d_in[11];
    const float* lc2w = (const float*)d_in[12];
    const float* g2 = (const float*)d_in[13], *b2 = (const float*)d_in[14];
    const float* m2 = (const float*)d_in[15], *v2 = (const float*)d_in[16];
    float* out = (float*)d_out;

    float *cc, *vv, *uu, *bns, *bnb;
    __half *Ah, *Al, *cfh, *xh;
    char* ws;
    cudaGetSymbolAddress((void**)&cc,  g_cc);
    cudaGetSymbolAddress((void**)&vv,  g_v);
    cudaGetSymbolAddress((void**)&uu,  g_u);
    cudaGetSymbolAddress((void**)&bns, g_bnscale);
    cudaGetSymbolAddress((void**)&bnb, g_bnbias);
    cudaGetSymbolAddress((void**)&Ah,  g_Ah);
    cudaGetSymbolAddress((void**)&Al,  g_Al);
    cudaGetSymbolAddress((void**)&cfh, g_cfh);
    cudaGetSymbolAddress((void**)&xh,  g_xh);
    cudaGetSymbolAddress((void**)&ws,  g_ws);
    float* Y = (float*)ws;
    float* Z = uu;                                  // reuse g_u after Cf is done
    __half* fh  = (__half*)(ws + FH_OFF);
    __half* u1h = (__half*)(ws + U1H_OFF);

    cudaFuncSetAttribute(mma_gemm<3,1>, cudaFuncAttributeMaxDynamicSharedMemorySize, GEMM_SMEM);
    cudaFuncSetAttribute(mma_gemm<8,1>, cudaFuncAttributeMaxDynamicSharedMemorySize, GEMM_SMEM);
    cudaFuncSetAttribute(mma_gemm<5,0>, cudaFuncAttributeMaxDynamicSharedMemorySize, GEMM_SMEM);
    cudaFuncSetAttribute(mma_gemm<7,0>, cudaFuncAttributeMaxDynamicSharedMemorySize, GEMM_SMEM);

    // 1. BN coefficients + permuted weight splits + x transpose
    bncoef_k<<<1, 512>>>(g1, b1, m1, v1, g2, b2, m2, v2);
    split_perm<<<(1179648 + 255) / 256, 256>>>(dc_w, Ah, Al, 512, 1179648);
    split_perm<<<(589824 + 255) / 256, 256>>>(lc1w, Ah + 1179648, Al + 1179648, 256, 589824);
    split_perm<<<(589824 + 255) / 256, 256>>>(lc2w, Ah + 1769472, Al + 1769472, 256, 589824);
    transpose_x_h<<<dim3(32, 8), dim3(32, 8)>>>(x);
    // 2. xu -> cc[0:256]
    upsample_k<<<NPIX, 256>>>(x);
    // 3. v = sigmoid(fm_w @ llf)
    sgemm_epi<1><<<dim3(128, 2), 256>>>(fm_w, llf, vv, nullptr, 256);
    // 4. u[c] = llf[c] @ v[c] + llf[c]
    chan_matmul<<<256, 256>>>(llf);
    // 5. Cf = fs_w @ u -> cc[256:512] (+ CfT -> g_v)
    sgemm_epi<6><<<dim3(128, 2), 256>>>(fs_w, uu, cc + (size_t)256 * NPIX, vv, 256);
    // 6. offsets = p_w @ im2col(cc) + p_b
    gemm_off<<<NPIX / 128, 512>>>(p_w, p_b);
    // 7. Cf pad+transpose -> fp16
    border_zero_cf<<<(516 * 256 + 255) / 256, 256>>>();
    transpose_pad_cf<<<dim3(128, 4, 8), dim3(32, 8)>>>();
    // 8. bilinear coords/weights
    coords_k<<<9 * NPIX / 256, 256>>>();
    // 9. Z[kp] = (dc_w_xu_kp @ x32^T)^T  (tiny GEMM, 1024 cols)
    mma_gemm<5,0><<<dim3(8, 2, 9), 256, GEMM_SMEM>>>(
        Ah, Al, xh, nullptr, Z, 256, 4608, 256, 1024, 0, nullptr, nullptr);
    // 10. Y[kp] = (dc_w_cf_kp @ Cfp^T)^T + upsample(Z[kp])
    mma_gemm<7,0><<<dim3(QPAD / 128, 2, 9), 256, GEMM_SMEM>>>(
        Ah, Al, cfh, nullptr, Y, 256, 4608, 256, QPAD, 256, Z, nullptr);
    // 11. famT = gathersum(Y) + CfT -> fp16 plane
    gathersum<<<NPIX, 256>>>(Y, vv);
    // 12. up1 = relu(bn1(lc1 (*) fam)) -> out + up1T fp16 plane (implicit im2col)
    mma_gemm<8,1><<<dim3(128, 2), 256, GEMM_SMEM>>>(
        Ah + 1179648, Al + 1179648, fh, out, u1h, 2304, 2304, 0, NPIX, 0, bns, bnb);
    // 13. up2 = relu(bn2(lc2 (*) up1)) -> out[256*NPIX:] (implicit im2col)
    mma_gemm<3,1><<<dim3(128, 2), 256, GEMM_SMEM>>>(
        Ah + 1769472, Al + 1769472, u1h, out + (size_t)256 * NPIX, nullptr,
        2304, 2304, 0, NPIX, 0, bns + 256, bnb + 256);
}